// round 8
// baseline (speedup 1.0000x reference)
#include <cuda_runtime.h>
#include <cuda_bf16.h>
#include <cuda_fp16.h>
#include <cstdint>

#define B_ 16
#define S_ 1024
#define N_ 4096
#define C_ 768
#define O_ 256
#define M_ (B_ * S_)   // 16384

// ---------------------------------------------------------------------------
// Scratch (__device__ globals; allocation-free rule). A is K-MAJOR, fp16.
// ---------------------------------------------------------------------------
__device__ int      g_idx[M_];
__device__ __half   g_Af[(size_t)C_ * M_];
__device__ __half   g_Bhi[O_ * C_];
__device__ __half   g_Blo[O_ * C_];

// ---------------------------------------------------------------------------
// Base-ISA (compute_103-safe) PTX helpers
// ---------------------------------------------------------------------------
__device__ __forceinline__ uint32_t smem_u32(const void* p) {
    uint32_t a;
    asm("{ .reg .u64 t; cvta.to.shared.u64 t, %1; cvt.u32.u64 %0, t; }" : "=r"(a) : "l"(p));
    return a;
}
__device__ __forceinline__ void cp16(uint32_t dst, const void* src) {
    asm volatile("cp.async.cg.shared.global [%0], [%1], 16;"
                 :: "r"(dst), "l"(src) : "memory");
}
#define CP_COMMIT() asm volatile("cp.async.commit_group;" ::: "memory")
#define CP_WAIT(n)  asm volatile("cp.async.wait_group %0;" :: "n"(n) : "memory")

__device__ __forceinline__ void ldsm4(uint32_t* r, uint32_t addr) {
    asm volatile("ldmatrix.sync.aligned.m8n8.x4.shared.b16 {%0,%1,%2,%3}, [%4];"
                 : "=r"(r[0]), "=r"(r[1]), "=r"(r[2]), "=r"(r[3]) : "r"(addr));
}
__device__ __forceinline__ void ldsm4t(uint32_t* r, uint32_t addr) {
    asm volatile("ldmatrix.sync.aligned.m8n8.x4.trans.shared.b16 {%0,%1,%2,%3}, [%4];"
                 : "=r"(r[0]), "=r"(r[1]), "=r"(r[2]), "=r"(r[3]) : "r"(addr));
}
__device__ __forceinline__ void mma_f16(float* c, const uint32_t* a, const uint32_t* b) {
    asm volatile("mma.sync.aligned.m16n8k16.row.col.f32.f16.f16.f32 "
                 "{%0,%1,%2,%3}, {%4,%5,%6,%7}, {%8,%9}, {%0,%1,%2,%3};"
                 : "+f"(c[0]), "+f"(c[1]), "+f"(c[2]), "+f"(c[3])
                 : "r"(a[0]), "r"(a[1]), "r"(a[2]), "r"(a[3]), "r"(b[0]), "r"(b[1]));
}

// ---------------------------------------------------------------------------
// Kernel 1: argmin (proven version, exact arithmetic mirror of reference).
// ---------------------------------------------------------------------------
__global__ __launch_bounds__(256) void argmin_kernel(const float* __restrict__ seed,
                                                     const float* __restrict__ pl) {
    extern __shared__ float4 p4[];                 // 4096 * 16B = 64KB
    __shared__ unsigned long long merge[4][64];
    const int bx  = blockIdx.x;
    const int b   = bx >> 4;                       // 16 blocks per batch
    const int tid = threadIdx.x;
    const int grp = tid >> 6;                      // 0..3
    const int sl  = tid & 63;
    const int s   = ((bx & 15) << 6) + sl;

    for (int n = tid; n < N_; n += 256) {
        const float* pp = pl + ((size_t)b * N_ + n) * 3;
        const float p0 = pp[0], p1 = pp[1], p2 = pp[2];
        const float spp = __fadd_rn(__fadd_rn(__fmul_rn(p0, p0), __fmul_rn(p1, p1)),
                                    __fmul_rn(p2, p2));
        p4[n] = make_float4(p0, p1, p2, spp);
    }
    const float* sp = seed + ((size_t)b * S_ + s) * 3;
    const float x0 = sp[0], x1 = sp[1], x2 = sp[2];
    const float sx = __fadd_rn(__fadd_rn(__fmul_rn(x0, x0), __fmul_rn(x1, x1)),
                               __fmul_rn(x2, x2));
    __syncthreads();

    unsigned long long best[4] = {~0ull, ~0ull, ~0ull, ~0ull};
    const int nb = grp * 1024;
#pragma unroll 4
    for (int n0 = 0; n0 < 1024; n0 += 4) {
#pragma unroll
        for (int j = 0; j < 4; j++) {
            const int n = nb + n0 + j;
            const float4 q = p4[n];
            const float dot = __fadd_rn(__fadd_rn(__fmul_rn(x0, q.x), __fmul_rn(x1, q.y)),
                                        __fmul_rn(x2, q.z));
            const float d2 = __fadd_rn(__fsub_rn(sx, __fadd_rn(dot, dot)), q.w);
            const unsigned u = __float_as_uint(d2);
            const unsigned ord = u ^ (((unsigned)((int)u >> 31)) | 0x80000000u);
            const unsigned long long key = ((unsigned long long)ord << 32) | (unsigned)n;
            if (key < best[j]) best[j] = key;
        }
    }
    unsigned long long k01 = best[0] < best[1] ? best[0] : best[1];
    unsigned long long k23 = best[2] < best[3] ? best[2] : best[3];
    unsigned long long k = k01 < k23 ? k01 : k23;
    merge[grp][sl] = k;
    __syncthreads();
    if (grp == 0) {
        unsigned long long k1 = merge[1][sl];
        unsigned long long k2 = merge[2][sl];
        unsigned long long k3 = merge[3][sl];
        if (k1 < k) k = k1;
        if (k2 < k) k = k2;
        if (k3 < k) k = k3;
        g_idx[b * S_ + s] = (int)(k & 0xFFFFFFFFu);
    }
}

// ---------------------------------------------------------------------------
// Kernel 2: gather, pipelined: group0 = idx + rows 0-1, group1 = rows 2-3.
// Process rows 0-1 while rows 2-3 are still loading.
// ---------------------------------------------------------------------------
__global__ __launch_bounds__(256) void gather_kernel(const float* __restrict__ f) {
    extern __shared__ char gs[];
    float* rows = reinterpret_cast<float*>(gs);            // 4 * 4096 floats
    int*   sidx = reinterpret_cast<int*>(gs + 65536);      // 1024 ints
    const uint32_t sb = smem_u32(gs);
    const int b   = blockIdx.x / 192;
    const int c0  = (blockIdx.x % 192) * 4;
    const int tid = threadIdx.x;

    const char* src = reinterpret_cast<const char*>(f + ((size_t)(b * C_ + c0)) * N_);

    // Group 0: idx + rows 0-1 (32KB)
    cp16(sb + 65536 + tid * 16, &g_idx[b * S_ + tid * 4]);
#pragma unroll
    for (int i = 0; i < 8; i++)
        cp16(sb + (tid + i * 256) * 16, src + (tid + i * 256) * 16);
    CP_COMMIT();
    // Group 1: rows 2-3 (32KB)
#pragma unroll
    for (int i = 8; i < 16; i++)
        cp16(sb + (tid + i * 256) * 16, src + (tid + i * 256) * 16);
    CP_COMMIT();

    CP_WAIT(1);
    __syncthreads();
#pragma unroll
    for (int c = 0; c < 2; c++) {
        const float* row = rows + c * 4096;
        const size_t obase = (size_t)(c0 + c) * M_ + b * S_;
        for (int s = tid; s < 1024; s += 256)
            g_Af[obase + s] = __float2half(row[sidx[s]]);
    }
    CP_WAIT(0);
    __syncthreads();
#pragma unroll
    for (int c = 2; c < 4; c++) {
        const float* row = rows + c * 4096;
        const size_t obase = (size_t)(c0 + c) * M_ + b * S_;
        for (int s = tid; s < 1024; s += 256)
            g_Af[obase + s] = __float2half(row[sidx[s]]);
    }
}

// ---------------------------------------------------------------------------
// Kernel 2b: split W into fp16 hi/lo.
// ---------------------------------------------------------------------------
__global__ __launch_bounds__(256) void wsplit_kernel(const float* __restrict__ W) {
    const int i = blockIdx.x * 256 + threadIdx.x;
    if (i < O_ * C_) {
        const float v = W[i];
        const __half h = __float2half(v);
        g_Bhi[i] = h;
        g_Blo[i] = __float2half(v - __half2float(h));
    }
}

// ---------------------------------------------------------------------------
// Kernel 3: mma.sync fp16 GEMM, 2-term W-split: D = Af*Bh + Af*Bl.
// CTA 128m x 64n, 256 thr, warps 4m x 2n, warp tile m32 x n32.
// k32 chunks (24 iterations -> half the barriers), 3-stage cp.async ring.
// A k-major: 32 krows x 256B data, 272B stride (17r mod 8 distinct: no
// conflicts). B row-major: 64 rows x 64B data, 112B stride (7r mod 8
// distinct: no conflicts).
// Stage: Af 8704 | Bh 7168 | Bl 7168 = 23040B; 3 stages = 69120B -> 3 CTAs/SM.
// ---------------------------------------------------------------------------
#define ARR_AF 0
#define ARR_BH 8704
#define ARR_BL 15872
#define STAGE  23040
#define GEMM_SMEM (3 * STAGE)

__global__ __launch_bounds__(256, 3) void gemm_kernel(const float* __restrict__ bias,
                                                      float* __restrict__ out) {
    extern __shared__ char smem[];
    const uint32_t sb = smem_u32(smem);
    const int tid  = threadIdx.x;
    const int lane = tid & 31;
    const int wid  = tid >> 5;
    const int warp_m = wid & 3;      // 4 m-warps (m32 each)
    const int warp_n = wid >> 2;     // 2 n-warps (n32 each)
    const int m0 = blockIdx.x * 128;
    const int n0 = blockIdx.y * 64;

    // cp.async assignment (uniform: 4 x 16B per thread).
    // A (k-major, 32 krows/chunk): krow = tid>>4 and +16; seg = tid&15.
    const int akrow = tid >> 4;
    const int aseg  = tid & 15;
    const __half* gA = g_Af + (size_t)akrow * M_ + m0 + aseg * 8;
    const uint32_t dA = (uint32_t)(akrow * 272 + aseg * 16);
    // B (row-major, 64 rows x 4 segs of 16B): brow = tid>>2, bseg = tid&3.
    const int brow = tid >> 2;
    const int bseg = tid & 3;
    const __half* gBh = g_Bhi + (size_t)(n0 + brow) * C_ + bseg * 8;
    const __half* gBl = g_Blo + (size_t)(n0 + brow) * C_ + bseg * 8;
    const uint32_t dB = (uint32_t)(brow * 112 + bseg * 16);

#define ISSUE(kc, stg)                                                    \
    do {                                                                  \
        const uint32_t s0 = sb + (stg) * STAGE;                           \
        const size_t ga = (size_t)(kc) * (32 * M_);                       \
        cp16(s0 + ARR_AF + dA,            gA + ga);                       \
        cp16(s0 + ARR_AF + dA + 16 * 272, gA + ga + (size_t)16 * M_);     \
        cp16(s0 + ARR_BH + dB, gBh + (kc) * 32);                          \
        cp16(s0 + ARR_BL + dB, gBl + (kc) * 32);                          \
    } while (0)

    ISSUE(0, 0); CP_COMMIT();
    ISSUE(1, 1); CP_COMMIT();

    float acc[2][4][4];
#pragma unroll
    for (int i = 0; i < 2; i++)
#pragma unroll
        for (int j = 0; j < 4; j++)
#pragma unroll
            for (int p = 0; p < 4; p++) acc[i][j][p] = 0.f;

    // ldmatrix.trans A addressing: k-rows x 272B, m-cols x 2B.
    const uint32_t aOff = (uint32_t)(((lane & 7) + ((lane >> 4) & 1) * 8) * 272
                                     + (warp_m * 32 + ((lane >> 3) & 1) * 8) * 2);
    // ldmatrix B addressing: 112B rows; k16-half at +32B, k-seg at +16B.
    const uint32_t bOff = (uint32_t)((warp_n * 32 + (lane & 7) + ((lane >> 4) << 3)) * 112
                                     + ((lane >> 3) & 1) * 16);

#pragma unroll 1
    for (int kc = 0; kc < 24; kc++) {
        CP_WAIT(1);                    // own groups: stage kc landed
        __syncthreads();               // stage kc visible; kc-1 reads done
        if (kc + 2 < 24) ISSUE(kc + 2, (kc + 2) % 3);
        CP_COMMIT();

        const uint32_t st = sb + (kc % 3) * STAGE;

#pragma unroll
        for (int h = 0; h < 2; h++) {  // two k16 halves of the k32 chunk
            uint32_t a[2][4];          // [mt][reg]
            ldsm4t(a[0], st + ARR_AF + aOff + h * (16 * 272));
            ldsm4t(a[1], st + ARR_AF + aOff + h * (16 * 272) + 32);

            uint32_t bb[2][2][4];      // [split][ntp][reg]
#pragma unroll
            for (int ntp = 0; ntp < 2; ntp++) {
                ldsm4(bb[0][ntp], st + ARR_BH + bOff + h * 32 + ntp * 16 * 112);
                ldsm4(bb[1][ntp], st + ARR_BL + bOff + h * 32 + ntp * 16 * 112);
            }

#pragma unroll
            for (int mt = 0; mt < 2; mt++)
#pragma unroll
                for (int nt = 0; nt < 4; nt++) {
                    const int ntp = nt >> 1, h2 = (nt & 1) * 2;
                    mma_f16(acc[mt][nt], a[mt], &bb[0][ntp][h2]);   // Af*Bh
                    mma_f16(acc[mt][nt], a[mt], &bb[1][ntp][h2]);   // Af*Bl
                }
        }
    }

    // Epilogue
    const int g  = lane >> 2;
    const int t4 = lane & 3;
    const int bbatch = m0 >> 10;
#pragma unroll
    for (int mt = 0; mt < 2; mt++) {
        const int m = m0 + warp_m * 32 + mt * 16 + g;
        const int slo = m & 1023;
#pragma unroll
        for (int nt = 0; nt < 4; nt++) {
            const int n = n0 + warp_n * 32 + nt * 8 + t4 * 2;
            const float b0v = __ldg(bias + n);
            const float b1v = __ldg(bias + n + 1);
            float* o0 = out + ((size_t)(bbatch * O_ + n)) * S_ + slo;
            float* o1 = out + ((size_t)(bbatch * O_ + n + 1)) * S_ + slo;
            o0[0] = acc[mt][nt][0] + b0v;
            o1[0] = acc[mt][nt][1] + b1v;
            o0[8] = acc[mt][nt][2] + b0v;
            o1[8] = acc[mt][nt][3] + b1v;
        }
    }
}

// ---------------------------------------------------------------------------
extern "C" void kernel_launch(void* const* d_in, const int* in_sizes, int n_in,
                              void* d_out, int out_size) {
    const float* seed = (const float*)d_in[0];   // [16,1024,3]
    const float* pl   = (const float*)d_in[1];   // [16,4096,3]
    const float* fl   = (const float*)d_in[2];   // [16,768,4096]
    const float* Wt   = (const float*)d_in[3];   // [256,768]
    const float* bias = (const float*)d_in[4];   // [256]
    float* out = (float*)d_out;                  // [16,256,1024]

    cudaFuncSetAttribute(argmin_kernel, cudaFuncAttributeMaxDynamicSharedMemorySize, 65536);
    cudaFuncSetAttribute(gather_kernel, cudaFuncAttributeMaxDynamicSharedMemorySize, 69632);
    cudaFuncSetAttribute(gemm_kernel, cudaFuncAttributeMaxDynamicSharedMemorySize, GEMM_SMEM);

    argmin_kernel<<<256, 256, 65536>>>(seed, pl);
    wsplit_kernel<<<(O_ * C_ + 255) / 256, 256>>>(Wt);
    gather_kernel<<<B_ * 192, 256, 69632>>>(fl);
    gemm_kernel<<<dim3(M_ / 128, O_ / 64), 256, GEMM_SMEM>>>(bias, out);
}

// round 9
// speedup vs baseline: 1.0116x; 1.0116x over previous
#include <cuda_runtime.h>
#include <cuda_bf16.h>
#include <cuda_fp16.h>
#include <cstdint>

#define B_ 16
#define S_ 1024
#define N_ 4096
#define C_ 768
#define O_ 256
#define M_ (B_ * S_)   // 16384

// ---------------------------------------------------------------------------
// Scratch (__device__ globals; allocation-free rule). A is K-MAJOR, fp16.
// ---------------------------------------------------------------------------
__device__ int      g_idx[M_];
__device__ __half   g_Af[(size_t)C_ * M_];
__device__ __half   g_Bhi[O_ * C_];
__device__ __half   g_Blo[O_ * C_];

// ---------------------------------------------------------------------------
// Base-ISA (compute_103-safe) PTX helpers
// ---------------------------------------------------------------------------
__device__ __forceinline__ uint32_t smem_u32(const void* p) {
    uint32_t a;
    asm("{ .reg .u64 t; cvta.to.shared.u64 t, %1; cvt.u32.u64 %0, t; }" : "=r"(a) : "l"(p));
    return a;
}
__device__ __forceinline__ void cp16(uint32_t dst, const void* src) {
    asm volatile("cp.async.cg.shared.global [%0], [%1], 16;"
                 :: "r"(dst), "l"(src) : "memory");
}
#define CP_COMMIT() asm volatile("cp.async.commit_group;" ::: "memory")
#define CP_WAIT(n)  asm volatile("cp.async.wait_group %0;" :: "n"(n) : "memory")

__device__ __forceinline__ void ldsm4(uint32_t* r, uint32_t addr) {
    asm volatile("ldmatrix.sync.aligned.m8n8.x4.shared.b16 {%0,%1,%2,%3}, [%4];"
                 : "=r"(r[0]), "=r"(r[1]), "=r"(r[2]), "=r"(r[3]) : "r"(addr));
}
__device__ __forceinline__ void ldsm4t(uint32_t* r, uint32_t addr) {
    asm volatile("ldmatrix.sync.aligned.m8n8.x4.trans.shared.b16 {%0,%1,%2,%3}, [%4];"
                 : "=r"(r[0]), "=r"(r[1]), "=r"(r[2]), "=r"(r[3]) : "r"(addr));
}
__device__ __forceinline__ void mma_f16(float* c, const uint32_t* a, const uint32_t* b) {
    asm volatile("mma.sync.aligned.m16n8k16.row.col.f32.f16.f16.f32 "
                 "{%0,%1,%2,%3}, {%4,%5,%6,%7}, {%8,%9}, {%0,%1,%2,%3};"
                 : "+f"(c[0]), "+f"(c[1]), "+f"(c[2]), "+f"(c[3])
                 : "r"(a[0]), "r"(a[1]), "r"(a[2]), "r"(a[3]), "r"(b[0]), "r"(b[1]));
}

// ---------------------------------------------------------------------------
// Kernel 1: argmin (proven version, exact arithmetic mirror of reference).
// ---------------------------------------------------------------------------
__global__ __launch_bounds__(256) void argmin_kernel(const float* __restrict__ seed,
                                                     const float* __restrict__ pl) {
    extern __shared__ float4 p4[];                 // 4096 * 16B = 64KB
    __shared__ unsigned long long merge[4][64];
    const int bx  = blockIdx.x;
    const int b   = bx >> 4;                       // 16 blocks per batch
    const int tid = threadIdx.x;
    const int grp = tid >> 6;                      // 0..3
    const int sl  = tid & 63;
    const int s   = ((bx & 15) << 6) + sl;

    for (int n = tid; n < N_; n += 256) {
        const float* pp = pl + ((size_t)b * N_ + n) * 3;
        const float p0 = pp[0], p1 = pp[1], p2 = pp[2];
        const float spp = __fadd_rn(__fadd_rn(__fmul_rn(p0, p0), __fmul_rn(p1, p1)),
                                    __fmul_rn(p2, p2));
        p4[n] = make_float4(p0, p1, p2, spp);
    }
    const float* sp = seed + ((size_t)b * S_ + s) * 3;
    const float x0 = sp[0], x1 = sp[1], x2 = sp[2];
    const float sx = __fadd_rn(__fadd_rn(__fmul_rn(x0, x0), __fmul_rn(x1, x1)),
                               __fmul_rn(x2, x2));
    __syncthreads();

    unsigned long long best[4] = {~0ull, ~0ull, ~0ull, ~0ull};
    const int nb = grp * 1024;
#pragma unroll 4
    for (int n0 = 0; n0 < 1024; n0 += 4) {
#pragma unroll
        for (int j = 0; j < 4; j++) {
            const int n = nb + n0 + j;
            const float4 q = p4[n];
            const float dot = __fadd_rn(__fadd_rn(__fmul_rn(x0, q.x), __fmul_rn(x1, q.y)),
                                        __fmul_rn(x2, q.z));
            const float d2 = __fadd_rn(__fsub_rn(sx, __fadd_rn(dot, dot)), q.w);
            const unsigned u = __float_as_uint(d2);
            const unsigned ord = u ^ (((unsigned)((int)u >> 31)) | 0x80000000u);
            const unsigned long long key = ((unsigned long long)ord << 32) | (unsigned)n;
            if (key < best[j]) best[j] = key;
        }
    }
    unsigned long long k01 = best[0] < best[1] ? best[0] : best[1];
    unsigned long long k23 = best[2] < best[3] ? best[2] : best[3];
    unsigned long long k = k01 < k23 ? k01 : k23;
    merge[grp][sl] = k;
    __syncthreads();
    if (grp == 0) {
        unsigned long long k1 = merge[1][sl];
        unsigned long long k2 = merge[2][sl];
        unsigned long long k3 = merge[3][sl];
        if (k1 < k) k = k1;
        if (k2 < k) k = k2;
        if (k3 < k) k = k3;
        g_idx[b * S_ + s] = (int)(k & 0xFFFFFFFFu);
    }
}

// ---------------------------------------------------------------------------
// Kernel 2: gather. 2 channels/block (6144 blocks -> ~5 CTAs/SM in flight),
// pipelined: group0 = idx + row0, group1 = row1.
// ---------------------------------------------------------------------------
__global__ __launch_bounds__(256) void gather_kernel(const float* __restrict__ f) {
    extern __shared__ char gs[];
    float* rows = reinterpret_cast<float*>(gs);            // 2 * 4096 floats
    int*   sidx = reinterpret_cast<int*>(gs + 32768);      // 1024 ints
    const uint32_t sb = smem_u32(gs);
    const int b   = blockIdx.x / 384;
    const int c0  = (blockIdx.x % 384) * 2;
    const int tid = threadIdx.x;

    const char* src = reinterpret_cast<const char*>(f + ((size_t)(b * C_ + c0)) * N_);

    // Group 0: idx (4KB) + row 0 (16KB)
    cp16(sb + 32768 + tid * 16, &g_idx[b * S_ + tid * 4]);
#pragma unroll
    for (int i = 0; i < 4; i++)
        cp16(sb + (tid + i * 256) * 16, src + (tid + i * 256) * 16);
    CP_COMMIT();
    // Group 1: row 1 (16KB)
#pragma unroll
    for (int i = 4; i < 8; i++)
        cp16(sb + (tid + i * 256) * 16, src + (tid + i * 256) * 16);
    CP_COMMIT();

    CP_WAIT(1);
    __syncthreads();
    {
        const float* row = rows;
        const size_t obase = (size_t)c0 * M_ + b * S_;
        for (int s = tid; s < 1024; s += 256)
            g_Af[obase + s] = __float2half(row[sidx[s]]);
    }
    CP_WAIT(0);
    __syncthreads();
    {
        const float* row = rows + 4096;
        const size_t obase = (size_t)(c0 + 1) * M_ + b * S_;
        for (int s = tid; s < 1024; s += 256)
            g_Af[obase + s] = __float2half(row[sidx[s]]);
    }
}

// ---------------------------------------------------------------------------
// Kernel 2b: split W into fp16 hi/lo.
// ---------------------------------------------------------------------------
__global__ __launch_bounds__(256) void wsplit_kernel(const float* __restrict__ W) {
    const int i = blockIdx.x * 256 + threadIdx.x;
    if (i < O_ * C_) {
        const float v = W[i];
        const __half h = __float2half(v);
        g_Bhi[i] = h;
        g_Blo[i] = __float2half(v - __half2float(h));
    }
}

// ---------------------------------------------------------------------------
// Kernel 3: mma.sync fp16 GEMM, 2-term W-split: D = Af*Bh + Af*Bl.
// Round-7 proven geometry: CTA 128m x 64n, 256 thr, warps 4m x 2n,
// warp tile m32 x n32, k16 chunks, 1 sync per chunk, 3 CTAs/SM.
// Ring deepened 4 -> 5 stages (only change vs round 7).
// Stage: Af 4352 | Bh 3072 | Bl 3072 = 10496B; 5 stages = 52480B.
// ---------------------------------------------------------------------------
#define ARR_AF 0
#define ARR_BH 4352
#define ARR_BL 7424
#define STAGE  10496
#define NSTG   5
#define GEMM_SMEM (NSTG * STAGE)

__global__ __launch_bounds__(256, 3) void gemm_kernel(const float* __restrict__ bias,
                                                      float* __restrict__ out) {
    extern __shared__ char smem[];
    const uint32_t sb = smem_u32(smem);
    const int tid  = threadIdx.x;
    const int lane = tid & 31;
    const int wid  = tid >> 5;
    const int warp_m = wid & 3;      // 4 m-warps (m32 each)
    const int warp_n = wid >> 2;     // 2 n-warps (n32 each)
    const int m0 = blockIdx.x * 128;
    const int n0 = blockIdx.y * 64;

    // cp.async assignment.
    // A (k-major): krow = tid>>4 (0..15), seg = tid&15.
    const int akrow = tid >> 4;
    const int aseg  = tid & 15;
    const __half* gA = g_Af + (size_t)akrow * M_ + m0 + aseg * 8;
    const uint32_t dA = (uint32_t)(akrow * 272 + aseg * 16);
    // B (row-major, 64 rows x 2 segs): threads 0..127 only.
    const int brow = (tid >> 1) & 63;
    const int bseg = tid & 1;
    const bool bact = tid < 128;
    const __half* gBh = g_Bhi + (size_t)(n0 + brow) * C_ + bseg * 8;
    const __half* gBl = g_Blo + (size_t)(n0 + brow) * C_ + bseg * 8;
    const uint32_t dB = (uint32_t)(brow * 48 + bseg * 16);

#define ISSUE(kc, stg)                                                    \
    do {                                                                  \
        const uint32_t s0 = sb + (stg) * STAGE;                           \
        cp16(s0 + ARR_AF + dA, gA + (size_t)(kc) * (16 * M_));            \
        if (bact) {                                                       \
            cp16(s0 + ARR_BH + dB, gBh + (kc) * 16);                      \
            cp16(s0 + ARR_BL + dB, gBl + (kc) * 16);                      \
        }                                                                 \
    } while (0)

    ISSUE(0, 0); CP_COMMIT();
    ISSUE(1, 1); CP_COMMIT();
    ISSUE(2, 2); CP_COMMIT();
    ISSUE(3, 3); CP_COMMIT();

    float acc[2][4][4];
#pragma unroll
    for (int i = 0; i < 2; i++)
#pragma unroll
        for (int j = 0; j < 4; j++)
#pragma unroll
            for (int p = 0; p < 4; p++) acc[i][j][p] = 0.f;

    // ldmatrix.trans A addressing (verified): k-rows x 272B, m-cols x 2B.
    const uint32_t aOff = (uint32_t)(((lane & 7) + ((lane >> 4) & 1) * 8) * 272
                                     + (warp_m * 32 + ((lane >> 3) & 1) * 8) * 2);
    // ldmatrix B addressing (verified): 48B rows.
    const uint32_t bOff = (uint32_t)((warp_n * 32 + (lane & 7) + ((lane >> 4) << 3)) * 48
                                     + ((lane >> 3) & 1) * 16);

#pragma unroll 1
    for (int kc = 0; kc < 48; kc++) {
        CP_WAIT(3);                    // own groups: stage kc landed
        __syncthreads();               // stage kc visible; kc-1 reads done
        if (kc + 4 < 48) ISSUE(kc + 4, (kc + 4) % NSTG);
        CP_COMMIT();

        const uint32_t st = sb + (kc % NSTG) * STAGE;

        uint32_t a[2][4];              // [mt][reg]
        ldsm4t(a[0], st + ARR_AF + aOff);
        ldsm4t(a[1], st + ARR_AF + aOff + 32);      // +16 m-cols

        uint32_t bb[2][2][4];          // [split][ntp][reg]
#pragma unroll
        for (int ntp = 0; ntp < 2; ntp++) {
            ldsm4(bb[0][ntp], st + ARR_BH + bOff + ntp * 16 * 48);
            ldsm4(bb[1][ntp], st + ARR_BL + bOff + ntp * 16 * 48);
        }

#pragma unroll
        for (int mt = 0; mt < 2; mt++)
#pragma unroll
            for (int nt = 0; nt < 4; nt++) {
                const int ntp = nt >> 1, h2 = (nt & 1) * 2;
                mma_f16(acc[mt][nt], a[mt], &bb[0][ntp][h2]);   // Af*Bh
                mma_f16(acc[mt][nt], a[mt], &bb[1][ntp][h2]);   // Af*Bl
            }
    }

    // Epilogue
    const int g  = lane >> 2;
    const int t4 = lane & 3;
    const int bbatch = m0 >> 10;
#pragma unroll
    for (int mt = 0; mt < 2; mt++) {
        const int m = m0 + warp_m * 32 + mt * 16 + g;
        const int slo = m & 1023;
#pragma unroll
        for (int nt = 0; nt < 4; nt++) {
            const int n = n0 + warp_n * 32 + nt * 8 + t4 * 2;
            const float b0v = __ldg(bias + n);
            const float b1v = __ldg(bias + n + 1);
            float* o0 = out + ((size_t)(bbatch * O_ + n)) * S_ + slo;
            float* o1 = out + ((size_t)(bbatch * O_ + n + 1)) * S_ + slo;
            o0[0] = acc[mt][nt][0] + b0v;
            o1[0] = acc[mt][nt][1] + b1v;
            o0[8] = acc[mt][nt][2] + b0v;
            o1[8] = acc[mt][nt][3] + b1v;
        }
    }
}

// ---------------------------------------------------------------------------
extern "C" void kernel_launch(void* const* d_in, const int* in_sizes, int n_in,
                              void* d_out, int out_size) {
    const float* seed = (const float*)d_in[0];   // [16,1024,3]
    const float* pl   = (const float*)d_in[1];   // [16,4096,3]
    const float* fl   = (const float*)d_in[2];   // [16,768,4096]
    const float* Wt   = (const float*)d_in[3];   // [256,768]
    const float* bias = (const float*)d_in[4];   // [256]
    float* out = (float*)d_out;                  // [16,256,1024]

    cudaFuncSetAttribute(argmin_kernel, cudaFuncAttributeMaxDynamicSharedMemorySize, 65536);
    cudaFuncSetAttribute(gather_kernel, cudaFuncAttributeMaxDynamicSharedMemorySize, 36864);
    cudaFuncSetAttribute(gemm_kernel, cudaFuncAttributeMaxDynamicSharedMemorySize, GEMM_SMEM);

    argmin_kernel<<<256, 256, 65536>>>(seed, pl);
    wsplit_kernel<<<(O_ * C_ + 255) / 256, 256>>>(Wt);
    gather_kernel<<<B_ * 384, 256, 36864>>>(fl);
    gemm_kernel<<<dim3(M_ / 128, O_ / 64), 256, GEMM_SMEM>>>(bias, out);
}

// round 10
// speedup vs baseline: 1.0981x; 1.0855x over previous
#include <cuda_runtime.h>
#include <cuda_bf16.h>
#include <cuda_fp16.h>
#include <cstdint>

#define B_ 16
#define S_ 1024
#define N_ 4096
#define C_ 768
#define O_ 256
#define M_ (B_ * S_)   // 16384

// ---------------------------------------------------------------------------
// Scratch (__device__ globals; allocation-free rule). A is K-MAJOR, fp16.
// ---------------------------------------------------------------------------
__device__ int      g_idx[M_];
__device__ __half   g_Af[(size_t)C_ * M_];
__device__ __half   g_Bf[O_ * C_];

// ---------------------------------------------------------------------------
// Base-ISA (compute_103-safe) PTX helpers
// ---------------------------------------------------------------------------
__device__ __forceinline__ uint32_t smem_u32(const void* p) {
    uint32_t a;
    asm("{ .reg .u64 t; cvta.to.shared.u64 t, %1; cvt.u32.u64 %0, t; }" : "=r"(a) : "l"(p));
    return a;
}
__device__ __forceinline__ void cp16(uint32_t dst, const void* src) {
    asm volatile("cp.async.cg.shared.global [%0], [%1], 16;"
                 :: "r"(dst), "l"(src) : "memory");
}
#define CP_COMMIT() asm volatile("cp.async.commit_group;" ::: "memory")
#define CP_WAIT(n)  asm volatile("cp.async.wait_group %0;" :: "n"(n) : "memory")

__device__ __forceinline__ void ldsm4(uint32_t* r, uint32_t addr) {
    asm volatile("ldmatrix.sync.aligned.m8n8.x4.shared.b16 {%0,%1,%2,%3}, [%4];"
                 : "=r"(r[0]), "=r"(r[1]), "=r"(r[2]), "=r"(r[3]) : "r"(addr));
}
__device__ __forceinline__ void ldsm4t(uint32_t* r, uint32_t addr) {
    asm volatile("ldmatrix.sync.aligned.m8n8.x4.trans.shared.b16 {%0,%1,%2,%3}, [%4];"
                 : "=r"(r[0]), "=r"(r[1]), "=r"(r[2]), "=r"(r[3]) : "r"(addr));
}
__device__ __forceinline__ void mma_f16(float* c, const uint32_t* a, const uint32_t* b) {
    asm volatile("mma.sync.aligned.m16n8k16.row.col.f32.f16.f16.f32 "
                 "{%0,%1,%2,%3}, {%4,%5,%6,%7}, {%8,%9}, {%0,%1,%2,%3};"
                 : "+f"(c[0]), "+f"(c[1]), "+f"(c[2]), "+f"(c[3])
                 : "r"(a[0]), "r"(a[1]), "r"(a[2]), "r"(a[3]), "r"(b[0]), "r"(b[1]));
}

// ---------------------------------------------------------------------------
// Kernel 1: argmin (proven version, exact arithmetic mirror of reference).
// ---------------------------------------------------------------------------
__global__ __launch_bounds__(256) void argmin_kernel(const float* __restrict__ seed,
                                                     const float* __restrict__ pl) {
    extern __shared__ float4 p4[];                 // 4096 * 16B = 64KB
    __shared__ unsigned long long merge[4][64];
    const int bx  = blockIdx.x;
    const int b   = bx >> 4;                       // 16 blocks per batch
    const int tid = threadIdx.x;
    const int grp = tid >> 6;                      // 0..3
    const int sl  = tid & 63;
    const int s   = ((bx & 15) << 6) + sl;

    for (int n = tid; n < N_; n += 256) {
        const float* pp = pl + ((size_t)b * N_ + n) * 3;
        const float p0 = pp[0], p1 = pp[1], p2 = pp[2];
        const float spp = __fadd_rn(__fadd_rn(__fmul_rn(p0, p0), __fmul_rn(p1, p1)),
                                    __fmul_rn(p2, p2));
        p4[n] = make_float4(p0, p1, p2, spp);
    }
    const float* sp = seed + ((size_t)b * S_ + s) * 3;
    const float x0 = sp[0], x1 = sp[1], x2 = sp[2];
    const float sx = __fadd_rn(__fadd_rn(__fmul_rn(x0, x0), __fmul_rn(x1, x1)),
                               __fmul_rn(x2, x2));
    __syncthreads();

    unsigned long long best[4] = {~0ull, ~0ull, ~0ull, ~0ull};
    const int nb = grp * 1024;
#pragma unroll 4
    for (int n0 = 0; n0 < 1024; n0 += 4) {
#pragma unroll
        for (int j = 0; j < 4; j++) {
            const int n = nb + n0 + j;
            const float4 q = p4[n];
            const float dot = __fadd_rn(__fadd_rn(__fmul_rn(x0, q.x), __fmul_rn(x1, q.y)),
                                        __fmul_rn(x2, q.z));
            const float d2 = __fadd_rn(__fsub_rn(sx, __fadd_rn(dot, dot)), q.w);
            const unsigned u = __float_as_uint(d2);
            const unsigned ord = u ^ (((unsigned)((int)u >> 31)) | 0x80000000u);
            const unsigned long long key = ((unsigned long long)ord << 32) | (unsigned)n;
            if (key < best[j]) best[j] = key;
        }
    }
    unsigned long long k01 = best[0] < best[1] ? best[0] : best[1];
    unsigned long long k23 = best[2] < best[3] ? best[2] : best[3];
    unsigned long long k = k01 < k23 ? k01 : k23;
    merge[grp][sl] = k;
    __syncthreads();
    if (grp == 0) {
        unsigned long long k1 = merge[1][sl];
        unsigned long long k2 = merge[2][sl];
        unsigned long long k3 = merge[3][sl];
        if (k1 < k) k = k1;
        if (k2 < k) k = k2;
        if (k3 < k) k = k3;
        g_idx[b * S_ + s] = (int)(k & 0xFFFFFFFFu);
    }
}

// ---------------------------------------------------------------------------
// Kernel 2: gather. 2 channels/block, pipelined (round-9 version).
// ---------------------------------------------------------------------------
__global__ __launch_bounds__(256) void gather_kernel(const float* __restrict__ f) {
    extern __shared__ char gs[];
    float* rows = reinterpret_cast<float*>(gs);            // 2 * 4096 floats
    int*   sidx = reinterpret_cast<int*>(gs + 32768);      // 1024 ints
    const uint32_t sb = smem_u32(gs);
    const int b   = blockIdx.x / 384;
    const int c0  = (blockIdx.x % 384) * 2;
    const int tid = threadIdx.x;

    const char* src = reinterpret_cast<const char*>(f + ((size_t)(b * C_ + c0)) * N_);

    cp16(sb + 32768 + tid * 16, &g_idx[b * S_ + tid * 4]);
#pragma unroll
    for (int i = 0; i < 4; i++)
        cp16(sb + (tid + i * 256) * 16, src + (tid + i * 256) * 16);
    CP_COMMIT();
#pragma unroll
    for (int i = 4; i < 8; i++)
        cp16(sb + (tid + i * 256) * 16, src + (tid + i * 256) * 16);
    CP_COMMIT();

    CP_WAIT(1);
    __syncthreads();
    {
        const float* row = rows;
        const size_t obase = (size_t)c0 * M_ + b * S_;
        for (int s = tid; s < 1024; s += 256)
            g_Af[obase + s] = __float2half(row[sidx[s]]);
    }
    CP_WAIT(0);
    __syncthreads();
    {
        const float* row = rows + 4096;
        const size_t obase = (size_t)(c0 + 1) * M_ + b * S_;
        for (int s = tid; s < 1024; s += 256)
            g_Af[obase + s] = __float2half(row[sidx[s]]);
    }
}

// ---------------------------------------------------------------------------
// Kernel 2b: round W to fp16 (single term).
// ---------------------------------------------------------------------------
__global__ __launch_bounds__(256) void wconv_kernel(const float* __restrict__ W) {
    const int i = blockIdx.x * 256 + threadIdx.x;
    if (i < O_ * C_) g_Bf[i] = __float2half(W[i]);
}

// ---------------------------------------------------------------------------
// Kernel 3: mma.sync fp16 GEMM, single term: D = Af*Bf.
// CTA 128m x 64n, 256 thr, warps 4m x 2n, warp tile m32 x n32, k16 chunks,
// 6-stage cp.async ring, 3 CTAs/SM. Register fragment double-buffering:
// iteration kc prefetches chunk kc+1's fragments before issuing kc's MMAs.
// Stage: Af 4352 | Bf 3072 = 7424B; 6 stages = 44544B.
// ---------------------------------------------------------------------------
#define ARR_AF 0
#define ARR_BF 4352
#define STAGE  7424
#define NSTG   6
#define GEMM_SMEM (NSTG * STAGE)

__global__ __launch_bounds__(256, 3) void gemm_kernel(const float* __restrict__ bias,
                                                      float* __restrict__ out) {
    extern __shared__ char smem[];
    const uint32_t sb = smem_u32(smem);
    const int tid  = threadIdx.x;
    const int lane = tid & 31;
    const int wid  = tid >> 5;
    const int warp_m = wid & 3;      // 4 m-warps (m32 each)
    const int warp_n = wid >> 2;     // 2 n-warps (n32 each)
    const int m0 = blockIdx.x * 128;
    const int n0 = blockIdx.y * 64;

    // cp.async assignment.
    const int akrow = tid >> 4;
    const int aseg  = tid & 15;
    const __half* gA = g_Af + (size_t)akrow * M_ + m0 + aseg * 8;
    const uint32_t dA = (uint32_t)(akrow * 272 + aseg * 16);
    const int brow = (tid >> 1) & 63;
    const int bseg = tid & 1;
    const bool bact = tid < 128;
    const __half* gB = g_Bf + (size_t)(n0 + brow) * C_ + bseg * 8;
    const uint32_t dB = (uint32_t)(brow * 48 + bseg * 16);

#define ISSUE(kc, stg)                                                    \
    do {                                                                  \
        const uint32_t s0 = sb + (stg) * STAGE;                           \
        cp16(s0 + ARR_AF + dA, gA + (size_t)(kc) * (16 * M_));            \
        if (bact) cp16(s0 + ARR_BF + dB, gB + (kc) * 16);                 \
    } while (0)

    ISSUE(0, 0); CP_COMMIT();
    ISSUE(1, 1); CP_COMMIT();
    ISSUE(2, 2); CP_COMMIT();
    ISSUE(3, 3); CP_COMMIT();
    ISSUE(4, 4); CP_COMMIT();

    float acc[2][4][4];
#pragma unroll
    for (int i = 0; i < 2; i++)
#pragma unroll
        for (int j = 0; j < 4; j++)
#pragma unroll
            for (int p = 0; p < 4; p++) acc[i][j][p] = 0.f;

    // ldmatrix.trans A addressing (verified): k-rows x 272B, m-cols x 2B.
    const uint32_t aOff = (uint32_t)(((lane & 7) + ((lane >> 4) & 1) * 8) * 272
                                     + (warp_m * 32 + ((lane >> 3) & 1) * 8) * 2);
    // ldmatrix B addressing (verified): 48B rows.
    const uint32_t bOff = (uint32_t)((warp_n * 32 + (lane & 7) + ((lane >> 4) << 3)) * 48
                                     + ((lane >> 3) & 1) * 16);

    uint32_t aF[2][2][4];            // [buf][mt][reg]
    uint32_t bF[2][2][4];            // [buf][ntp][reg]

    // Prologue: stage 0 -> buf 0 fragments.
    CP_WAIT(4);
    __syncthreads();
    ldsm4t(aF[0][0], sb + ARR_AF + aOff);
    ldsm4t(aF[0][1], sb + ARR_AF + aOff + 32);
    ldsm4(bF[0][0], sb + ARR_BF + bOff);
    ldsm4(bF[0][1], sb + ARR_BF + bOff + 16 * 48);

#define STEP(c, n, kc)                                                     \
    do {                                                                   \
        if ((kc) + 1 < 48) {                                               \
            CP_WAIT(3);                                                    \
            __syncthreads();                                               \
            const uint32_t stn = sb + (((kc) + 1) % NSTG) * STAGE;         \
            ldsm4t(aF[n][0], stn + ARR_AF + aOff);                         \
            ldsm4t(aF[n][1], stn + ARR_AF + aOff + 32);                    \
            ldsm4(bF[n][0], stn + ARR_BF + bOff);                          \
            ldsm4(bF[n][1], stn + ARR_BF + bOff + 16 * 48);                \
            if ((kc) + 5 < 48) ISSUE((kc) + 5, ((kc) + 5) % NSTG);         \
            CP_COMMIT();                                                   \
        }                                                                  \
        _Pragma("unroll")                                                  \
        for (int mt = 0; mt < 2; mt++)                                     \
            _Pragma("unroll")                                              \
            for (int nt = 0; nt < 4; nt++)                                 \
                mma_f16(acc[mt][nt], aF[c][mt],                            \
                        &bF[c][nt >> 1][(nt & 1) * 2]);                    \
    } while (0)

#pragma unroll 1
    for (int kc = 0; kc < 48; kc += 2) {
        STEP(0, 1, kc);
        STEP(1, 0, kc + 1);
    }

    // Epilogue
    const int g  = lane >> 2;
    const int t4 = lane & 3;
    const int bbatch = m0 >> 10;
#pragma unroll
    for (int mt = 0; mt < 2; mt++) {
        const int m = m0 + warp_m * 32 + mt * 16 + g;
        const int slo = m & 1023;
#pragma unroll
        for (int nt = 0; nt < 4; nt++) {
            const int n = n0 + warp_n * 32 + nt * 8 + t4 * 2;
            const float b0v = __ldg(bias + n);
            const float b1v = __ldg(bias + n + 1);
            float* o0 = out + ((size_t)(bbatch * O_ + n)) * S_ + slo;
            float* o1 = out + ((size_t)(bbatch * O_ + n + 1)) * S_ + slo;
            o0[0] = acc[mt][nt][0] + b0v;
            o1[0] = acc[mt][nt][1] + b1v;
            o0[8] = acc[mt][nt][2] + b0v;
            o1[8] = acc[mt][nt][3] + b1v;
        }
    }
}

// ---------------------------------------------------------------------------
extern "C" void kernel_launch(void* const* d_in, const int* in_sizes, int n_in,
                              void* d_out, int out_size) {
    const float* seed = (const float*)d_in[0];   // [16,1024,3]
    const float* pl   = (const float*)d_in[1];   // [16,4096,3]
    const float* fl   = (const float*)d_in[2];   // [16,768,4096]
    const float* Wt   = (const float*)d_in[3];   // [256,768]
    const float* bias = (const float*)d_in[4];   // [256]
    float* out = (float*)d_out;                  // [16,256,1024]

    cudaFuncSetAttribute(argmin_kernel, cudaFuncAttributeMaxDynamicSharedMemorySize, 65536);
    cudaFuncSetAttribute(gather_kernel, cudaFuncAttributeMaxDynamicSharedMemorySize, 36864);
    cudaFuncSetAttribute(gemm_kernel, cudaFuncAttributeMaxDynamicSharedMemorySize, GEMM_SMEM);

    argmin_kernel<<<256, 256, 65536>>>(seed, pl);
    wconv_kernel<<<(O_ * C_ + 255) / 256, 256>>>(Wt);
    gather_kernel<<<B_ * 384, 256, 36864>>>(fl);
    gemm_kernel<<<dim3(M_ / 128, O_ / 64), 256, GEMM_SMEM>>>(bias, out);
}

// round 12
// speedup vs baseline: 1.1123x; 1.0130x over previous
#include <cuda_runtime.h>
#include <cuda_bf16.h>
#include <cuda_fp16.h>
#include <cstdint>

#define B_ 16
#define S_ 1024
#define N_ 4096
#define C_ 768
#define O_ 256
#define M_ (B_ * S_)   // 16384

// ---------------------------------------------------------------------------
// Scratch (__device__ globals; allocation-free rule). A is K-MAJOR, fp16.
// ---------------------------------------------------------------------------
__device__ int      g_idx[M_];
__device__ __half   g_Af[(size_t)C_ * M_];
__device__ __half   g_Bf[O_ * C_];

// ---------------------------------------------------------------------------
// Base-ISA (compute_103-safe) PTX helpers
// ---------------------------------------------------------------------------
__device__ __forceinline__ uint32_t smem_u32(const void* p) {
    uint32_t a;
    asm("{ .reg .u64 t; cvta.to.shared.u64 t, %1; cvt.u32.u64 %0, t; }" : "=r"(a) : "l"(p));
    return a;
}
__device__ __forceinline__ void cp16(uint32_t dst, const void* src) {
    asm volatile("cp.async.cg.shared.global [%0], [%1], 16;"
                 :: "r"(dst), "l"(src) : "memory");
}
#define CP_COMMIT() asm volatile("cp.async.commit_group;" ::: "memory")
#define CP_WAIT(n)  asm volatile("cp.async.wait_group %0;" :: "n"(n) : "memory")

__device__ __forceinline__ void ldsm4(uint32_t* r, uint32_t addr) {
    asm volatile("ldmatrix.sync.aligned.m8n8.x4.shared.b16 {%0,%1,%2,%3}, [%4];"
                 : "=r"(r[0]), "=r"(r[1]), "=r"(r[2]), "=r"(r[3]) : "r"(addr));
}
__device__ __forceinline__ void ldsm4t(uint32_t* r, uint32_t addr) {
    asm volatile("ldmatrix.sync.aligned.m8n8.x4.trans.shared.b16 {%0,%1,%2,%3}, [%4];"
                 : "=r"(r[0]), "=r"(r[1]), "=r"(r[2]), "=r"(r[3]) : "r"(addr));
}
__device__ __forceinline__ void mma_f16(float* c, const uint32_t* a, const uint32_t* b) {
    asm volatile("mma.sync.aligned.m16n8k16.row.col.f32.f16.f16.f32 "
                 "{%0,%1,%2,%3}, {%4,%5,%6,%7}, {%8,%9}, {%0,%1,%2,%3};"
                 : "+f"(c[0]), "+f"(c[1]), "+f"(c[2]), "+f"(c[3])
                 : "r"(a[0]), "r"(a[1]), "r"(a[2]), "r"(a[3]), "r"(b[0]), "r"(b[1]));
}

// ---------------------------------------------------------------------------
// Kernel 1: argmin (proven version, exact arithmetic mirror of reference).
// ---------------------------------------------------------------------------
__global__ __launch_bounds__(256) void argmin_kernel(const float* __restrict__ seed,
                                                     const float* __restrict__ pl) {
    extern __shared__ float4 p4[];                 // 4096 * 16B = 64KB
    __shared__ unsigned long long merge[4][64];
    const int bx  = blockIdx.x;
    const int b   = bx >> 4;                       // 16 blocks per batch
    const int tid = threadIdx.x;
    const int grp = tid >> 6;                      // 0..3
    const int sl  = tid & 63;
    const int s   = ((bx & 15) << 6) + sl;

    for (int n = tid; n < N_; n += 256) {
        const float* pp = pl + ((size_t)b * N_ + n) * 3;
        const float p0 = pp[0], p1 = pp[1], p2 = pp[2];
        const float spp = __fadd_rn(__fadd_rn(__fmul_rn(p0, p0), __fmul_rn(p1, p1)),
                                    __fmul_rn(p2, p2));
        p4[n] = make_float4(p0, p1, p2, spp);
    }
    const float* sp = seed + ((size_t)b * S_ + s) * 3;
    const float x0 = sp[0], x1 = sp[1], x2 = sp[2];
    const float sx = __fadd_rn(__fadd_rn(__fmul_rn(x0, x0), __fmul_rn(x1, x1)),
                               __fmul_rn(x2, x2));
    __syncthreads();

    unsigned long long best[4] = {~0ull, ~0ull, ~0ull, ~0ull};
    const int nb = grp * 1024;
#pragma unroll 4
    for (int n0 = 0; n0 < 1024; n0 += 4) {
#pragma unroll
        for (int j = 0; j < 4; j++) {
            const int n = nb + n0 + j;
            const float4 q = p4[n];
            const float dot = __fadd_rn(__fadd_rn(__fmul_rn(x0, q.x), __fmul_rn(x1, q.y)),
                                        __fmul_rn(x2, q.z));
            const float d2 = __fadd_rn(__fsub_rn(sx, __fadd_rn(dot, dot)), q.w);
            const unsigned u = __float_as_uint(d2);
            const unsigned ord = u ^ (((unsigned)((int)u >> 31)) | 0x80000000u);
            const unsigned long long key = ((unsigned long long)ord << 32) | (unsigned)n;
            if (key < best[j]) best[j] = key;
        }
    }
    unsigned long long k01 = best[0] < best[1] ? best[0] : best[1];
    unsigned long long k23 = best[2] < best[3] ? best[2] : best[3];
    unsigned long long k = k01 < k23 ? k01 : k23;
    merge[grp][sl] = k;
    __syncthreads();
    if (grp == 0) {
        unsigned long long k1 = merge[1][sl];
        unsigned long long k2 = merge[2][sl];
        unsigned long long k3 = merge[3][sl];
        if (k1 < k) k = k1;
        if (k2 < k) k = k2;
        if (k3 < k) k = k3;
        g_idx[b * S_ + s] = (int)(k & 0xFFFFFFFFu);
    }
}

// ---------------------------------------------------------------------------
// Kernel 2: gather. 4 channel rows/block, rolling cp.async pipeline:
// groups {idx+row0, row1, row2, row3} all issued up-front (64KB in flight),
// rows processed as they land (wait 3/2/1/0). Per thread: int4 idx read,
// 4 independent LDS lookups, pack 4 halves -> one uint2 (8B) store.
// Each 16KB row = 1024 segments of 16B: segment index = c*1024 + tid + i*256.
// smem: rows 65536 + idx 4096 = 69632B -> 3 blocks/SM.
// ---------------------------------------------------------------------------
__global__ __launch_bounds__(256) void gather_kernel(const float* __restrict__ f) {
    extern __shared__ char gs[];
    float* rows = reinterpret_cast<float*>(gs);            // 4 * 4096 floats
    int*   sidx = reinterpret_cast<int*>(gs + 65536);      // 1024 ints
    const uint32_t sb = smem_u32(gs);
    const int b   = blockIdx.x / 192;
    const int c0  = (blockIdx.x % 192) * 4;
    const int tid = threadIdx.x;

    const char* src = reinterpret_cast<const char*>(f + ((size_t)(b * C_ + c0)) * N_);

    // Group 0: idx (4KB) + row 0 (16KB = segments 0..1023)
    cp16(sb + 65536 + tid * 16, &g_idx[b * S_ + tid * 4]);
#pragma unroll
    for (int i = 0; i < 4; i++)
        cp16(sb + (tid + i * 256) * 16, src + (tid + i * 256) * 16);
    CP_COMMIT();
    // Groups 1..3: rows 1..3 (segments c*1024 .. c*1024+1023)
#pragma unroll
    for (int c = 1; c < 4; c++) {
#pragma unroll
        for (int i = 0; i < 4; i++)
            cp16(sb + (c * 1024 + tid + i * 256) * 16,
                 src + (size_t)(c * 1024 + tid + i * 256) * 16);
        CP_COMMIT();
    }

    // Row 0 (idx also ready after this wait)
    CP_WAIT(3);
    __syncthreads();
    const int4 i4 = reinterpret_cast<const int4*>(sidx)[tid];

#define GPROC(c)                                                            \
    do {                                                                    \
        const float* row = rows + (c) * 4096;                               \
        const __half h0 = __float2half(row[i4.x]);                          \
        const __half h1 = __float2half(row[i4.y]);                          \
        const __half h2 = __float2half(row[i4.z]);                          \
        const __half h3 = __float2half(row[i4.w]);                          \
        uint2 pk;                                                           \
        pk.x = (uint32_t)__half_as_ushort(h0) |                             \
               ((uint32_t)__half_as_ushort(h1) << 16);                      \
        pk.y = (uint32_t)__half_as_ushort(h2) |                             \
               ((uint32_t)__half_as_ushort(h3) << 16);                      \
        *reinterpret_cast<uint2*>(                                          \
            &g_Af[(size_t)(c0 + (c)) * M_ + b * S_ + tid * 4]) = pk;        \
    } while (0)

    GPROC(0);
    CP_WAIT(2); __syncthreads();
    GPROC(1);
    CP_WAIT(1); __syncthreads();
    GPROC(2);
    CP_WAIT(0); __syncthreads();
    GPROC(3);
#undef GPROC
}

// ---------------------------------------------------------------------------
// Kernel 2b: round W to fp16 (single term).
// ---------------------------------------------------------------------------
__global__ __launch_bounds__(256) void wconv_kernel(const float* __restrict__ W) {
    const int i = blockIdx.x * 256 + threadIdx.x;
    if (i < O_ * C_) g_Bf[i] = __float2half(W[i]);
}

// ---------------------------------------------------------------------------
// Kernel 3: mma.sync fp16 GEMM, single term: D = Af*Bf.
// CTA 128m x 64n, 256 thr, warps 4m x 2n, warp tile m32 x n32, k16 chunks,
// 8-stage cp.async ring (power-of-2: &7), 3 CTAs/SM, register fragment
// double-buffering (prefetch kc+1 fragments before kc MMAs).
// Stage: Af 4352 | Bf 3072 = 7424B; 8 stages = 59392B.
// ---------------------------------------------------------------------------
#define ARR_AF 0
#define ARR_BF 4352
#define STAGE  7424
#define NSTG   8
#define GEMM_SMEM (NSTG * STAGE)

__global__ __launch_bounds__(256, 3) void gemm_kernel(const float* __restrict__ bias,
                                                      float* __restrict__ out) {
    extern __shared__ char smem[];
    const uint32_t sb = smem_u32(smem);
    const int tid  = threadIdx.x;
    const int lane = tid & 31;
    const int wid  = tid >> 5;
    const int warp_m = wid & 3;      // 4 m-warps (m32 each)
    const int warp_n = wid >> 2;     // 2 n-warps (n32 each)
    const int m0 = blockIdx.x * 128;
    const int n0 = blockIdx.y * 64;

    // cp.async assignment.
    const int akrow = tid >> 4;
    const int aseg  = tid & 15;
    const __half* gA = g_Af + (size_t)akrow * M_ + m0 + aseg * 8;
    const uint32_t dA = (uint32_t)(akrow * 272 + aseg * 16);
    const int brow = (tid >> 1) & 63;
    const int bseg = tid & 1;
    const bool bact = tid < 128;
    const __half* gB = g_Bf + (size_t)(n0 + brow) * C_ + bseg * 8;
    const uint32_t dB = (uint32_t)(brow * 48 + bseg * 16);

#define ISSUE(kc, stg)                                                    \
    do {                                                                  \
        const uint32_t s0 = sb + (stg) * STAGE;                           \
        cp16(s0 + ARR_AF + dA, gA + (size_t)(kc) * (16 * M_));            \
        if (bact) cp16(s0 + ARR_BF + dB, gB + (kc) * 16);                 \
    } while (0)

    ISSUE(0, 0); CP_COMMIT();
    ISSUE(1, 1); CP_COMMIT();
    ISSUE(2, 2); CP_COMMIT();
    ISSUE(3, 3); CP_COMMIT();
    ISSUE(4, 4); CP_COMMIT();

    float acc[2][4][4];
#pragma unroll
    for (int i = 0; i < 2; i++)
#pragma unroll
        for (int j = 0; j < 4; j++)
#pragma unroll
            for (int p = 0; p < 4; p++) acc[i][j][p] = 0.f;

    // ldmatrix.trans A addressing (verified): k-rows x 272B, m-cols x 2B.
    const uint32_t aOff = (uint32_t)(((lane & 7) + ((lane >> 4) & 1) * 8) * 272
                                     + (warp_m * 32 + ((lane >> 3) & 1) * 8) * 2);
    // ldmatrix B addressing (verified): 48B rows.
    const uint32_t bOff = (uint32_t)((warp_n * 32 + (lane & 7) + ((lane >> 4) << 3)) * 48
                                     + ((lane >> 3) & 1) * 16);

    uint32_t aF[2][2][4];            // [buf][mt][reg]
    uint32_t bF[2][2][4];            // [buf][ntp][reg]

    // Prologue: stage 0 -> buf 0 fragments.
    CP_WAIT(4);
    __syncthreads();
    ldsm4t(aF[0][0], sb + ARR_AF + aOff);
    ldsm4t(aF[0][1], sb + ARR_AF + aOff + 32);
    ldsm4(bF[0][0], sb + ARR_BF + bOff);
    ldsm4(bF[0][1], sb + ARR_BF + bOff + 16 * 48);

#define STEP(c, n, kc)                                                     \
    do {                                                                   \
        if ((kc) + 1 < 48) {                                               \
            CP_WAIT(3);                                                    \
            __syncthreads();                                               \
            const uint32_t stn = sb + (((kc) + 1) & 7) * STAGE;            \
            ldsm4t(aF[n][0], stn + ARR_AF + aOff);                         \
            ldsm4t(aF[n][1], stn + ARR_AF + aOff + 32);                    \
            ldsm4(bF[n][0], stn + ARR_BF + bOff);                          \
            ldsm4(bF[n][1], stn + ARR_BF + bOff + 16 * 48);                \
            if ((kc) + 5 < 48) ISSUE((kc) + 5, ((kc) + 5) & 7);            \
            CP_COMMIT();                                                   \
        }                                                                  \
        _Pragma("unroll")                                                  \
        for (int mt = 0; mt < 2; mt++)                                     \
            _Pragma("unroll")                                              \
            for (int nt = 0; nt < 4; nt++)                                 \
                mma_f16(acc[mt][nt], aF[c][mt],                            \
                        &bF[c][nt >> 1][(nt & 1) * 2]);                    \
    } while (0)

#pragma unroll 1
    for (int kc = 0; kc < 48; kc += 2) {
        STEP(0, 1, kc);
        STEP(1, 0, kc + 1);
    }

    // Epilogue
    const int g  = lane >> 2;
    const int t4 = lane & 3;
    const int bbatch = m0 >> 10;
#pragma unroll
    for (int mt = 0; mt < 2; mt++) {
        const int m = m0 + warp_m * 32 + mt * 16 + g;
        const int slo = m & 1023;
#pragma unroll
        for (int nt = 0; nt < 4; nt++) {
            const int n = n0 + warp_n * 32 + nt * 8 + t4 * 2;
            const float b0v = __ldg(bias + n);
            const float b1v = __ldg(bias + n + 1);
            float* o0 = out + ((size_t)(bbatch * O_ + n)) * S_ + slo;
            float* o1 = out + ((size_t)(bbatch * O_ + n + 1)) * S_ + slo;
            o0[0] = acc[mt][nt][0] + b0v;
            o1[0] = acc[mt][nt][1] + b1v;
            o0[8] = acc[mt][nt][2] + b0v;
            o1[8] = acc[mt][nt][3] + b1v;
        }
    }
}

// ---------------------------------------------------------------------------
extern "C" void kernel_launch(void* const* d_in, const int* in_sizes, int n_in,
                              void* d_out, int out_size) {
    const float* seed = (const float*)d_in[0];   // [16,1024,3]
    const float* pl   = (const float*)d_in[1];   // [16,4096,3]
    const float* fl   = (const float*)d_in[2];   // [16,768,4096]
    const float* Wt   = (const float*)d_in[3];   // [256,768]
    const float* bias = (const float*)d_in[4];   // [256]
    float* out = (float*)d_out;                  // [16,256,1024]

    cudaFuncSetAttribute(argmin_kernel, cudaFuncAttributeMaxDynamicSharedMemorySize, 65536);
    cudaFuncSetAttribute(gather_kernel, cudaFuncAttributeMaxDynamicSharedMemorySize, 69632);
    cudaFuncSetAttribute(gemm_kernel, cudaFuncAttributeMaxDynamicSharedMemorySize, GEMM_SMEM);

    argmin_kernel<<<256, 256, 65536>>>(seed, pl);
    wconv_kernel<<<(O_ * C_ + 255) / 256, 256>>>(Wt);
    gather_kernel<<<B_ * 192, 256, 69632>>>(fl);
    gemm_kernel<<<dim3(M_ / 128, O_ / 64), 256, GEMM_SMEM>>>(bias, out);
}

// round 13
// speedup vs baseline: 1.2930x; 1.1625x over previous
#include <cuda_runtime.h>
#include <cuda_bf16.h>
#include <cuda_fp16.h>
#include <cstdint>

#define B_ 16
#define S_ 1024
#define N_ 4096
#define C_ 768
#define O_ 256
#define M_ (B_ * S_)   // 16384

// ---------------------------------------------------------------------------
// Scratch (__device__ globals; allocation-free rule). A is K-MAJOR, fp16.
// ---------------------------------------------------------------------------
__device__ int      g_idx[M_];
__device__ __half   g_Af[(size_t)C_ * M_];
__device__ __half   g_Bf[O_ * C_];

// ---------------------------------------------------------------------------
// Base-ISA (compute_103-safe) PTX helpers
// ---------------------------------------------------------------------------
__device__ __forceinline__ uint32_t smem_u32(const void* p) {
    uint32_t a;
    asm("{ .reg .u64 t; cvta.to.shared.u64 t, %1; cvt.u32.u64 %0, t; }" : "=r"(a) : "l"(p));
    return a;
}
__device__ __forceinline__ void cp16(uint32_t dst, const void* src) {
    asm volatile("cp.async.cg.shared.global [%0], [%1], 16;"
                 :: "r"(dst), "l"(src) : "memory");
}
#define CP_COMMIT() asm volatile("cp.async.commit_group;" ::: "memory")
#define CP_WAIT(n)  asm volatile("cp.async.wait_group %0;" :: "n"(n) : "memory")

__device__ __forceinline__ void ldsm4(uint32_t* r, uint32_t addr) {
    asm volatile("ldmatrix.sync.aligned.m8n8.x4.shared.b16 {%0,%1,%2,%3}, [%4];"
                 : "=r"(r[0]), "=r"(r[1]), "=r"(r[2]), "=r"(r[3]) : "r"(addr));
}
__device__ __forceinline__ void ldsm4t(uint32_t* r, uint32_t addr) {
    asm volatile("ldmatrix.sync.aligned.m8n8.x4.trans.shared.b16 {%0,%1,%2,%3}, [%4];"
                 : "=r"(r[0]), "=r"(r[1]), "=r"(r[2]), "=r"(r[3]) : "r"(addr));
}
__device__ __forceinline__ void mma_f16(float* c, const uint32_t* a, const uint32_t* b) {
    asm volatile("mma.sync.aligned.m16n8k16.row.col.f32.f16.f16.f32 "
                 "{%0,%1,%2,%3}, {%4,%5,%6,%7}, {%8,%9}, {%0,%1,%2,%3};"
                 : "+f"(c[0]), "+f"(c[1]), "+f"(c[2]), "+f"(c[3])
                 : "r"(a[0]), "r"(a[1]), "r"(a[2]), "r"(a[3]), "r"(b[0]), "r"(b[1]));
}

// ---- packed fp32x2 (sm_100-family base ISA; per-lane IEEE rn, identical to
//      __fmul_rn/__fadd_rn — required for bit-exact argmin mirroring) --------
typedef unsigned long long ull;
__device__ __forceinline__ ull pk2(float a, float b) {
    ull r;
    asm("mov.b64 %0, {%1, %2};" : "=l"(r) : "r"(__float_as_uint(a)), "r"(__float_as_uint(b)));
    return r;
}
__device__ __forceinline__ ull bc2(float v) {
    ull r;
    asm("mov.b64 %0, {%1, %1};" : "=l"(r) : "r"(__float_as_uint(v)));
    return r;
}
__device__ __forceinline__ ull mul2(ull a, ull b) {
    ull d; asm("mul.rn.f32x2 %0, %1, %2;" : "=l"(d) : "l"(a), "l"(b)); return d;
}
__device__ __forceinline__ ull add2(ull a, ull b) {
    ull d; asm("add.rn.f32x2 %0, %1, %2;" : "=l"(d) : "l"(a), "l"(b)); return d;
}
// a - b == a + (-b) exactly (IEEE sign flip + rn add == rn sub)
__device__ __forceinline__ ull sub2(ull a, ull b) {
    return add2(a, b ^ 0x8000000080000000ull);
}
__device__ __forceinline__ void unpk2(float& lo, float& hi, ull v) {
    unsigned a, b;
    asm("mov.b64 {%0, %1}, %2;" : "=r"(a), "=r"(b) : "l"(v));
    lo = __uint_as_float(a); hi = __uint_as_float(b);
}
__device__ __forceinline__ ull mkkey(float d2, int n) {
    const unsigned u = __float_as_uint(d2);
    const unsigned ord = u ^ (((unsigned)((int)u >> 31)) | 0x80000000u);
    return ((ull)ord << 32) | (unsigned)n;
}

// ---------------------------------------------------------------------------
// Kernel 1: argmin, f32x2-packed: each thread evaluates TWO seeds per point
// (point coords broadcast into both lanes). Arithmetic is the exact unfused
// mul/add sequence of the reference per lane. Warp w scans points
// [w*512, w*512+512); 2 chains per seed (n parity); exact tie semantics via
// (ord(d2), n) packed keys at merge time.
// ---------------------------------------------------------------------------
__global__ __launch_bounds__(256) void argmin_kernel(const float* __restrict__ seed,
                                                     const float* __restrict__ pl) {
    extern __shared__ float4 p4[];                 // 4096 * 16B = 64KB
    __shared__ ull mg[8][64];                      // 4KB merge
    const int bx   = blockIdx.x;
    const int b    = bx >> 4;                      // 16 blocks per batch
    const int tid  = threadIdx.x;
    const int w    = tid >> 5;                     // warp = point-group, 0..7
    const int lane = tid & 31;
    const int sbase = (bx & 15) << 6;              // 64 seeds per block

    for (int n = tid; n < N_; n += 256) {
        const float* pp = pl + ((size_t)b * N_ + n) * 3;
        const float p0 = pp[0], p1 = pp[1], p2 = pp[2];
        const float spp = __fadd_rn(__fadd_rn(__fmul_rn(p0, p0), __fmul_rn(p1, p1)),
                                    __fmul_rn(p2, p2));
        p4[n] = make_float4(p0, p1, p2, spp);
    }

    // Two seeds per thread: a = sbase+lane, b2 = sbase+32+lane.
    const float* sa = seed + ((size_t)b * S_ + sbase + lane) * 3;
    const float* sc = seed + ((size_t)b * S_ + sbase + 32 + lane) * 3;
    const float xa0 = sa[0], xa1 = sa[1], xa2 = sa[2];
    const float xb0 = sc[0], xb1 = sc[1], xb2 = sc[2];
    const float sxa = __fadd_rn(__fadd_rn(__fmul_rn(xa0, xa0), __fmul_rn(xa1, xa1)),
                                __fmul_rn(xa2, xa2));
    const float sxb = __fadd_rn(__fadd_rn(__fmul_rn(xb0, xb0), __fmul_rn(xb1, xb1)),
                                __fmul_rn(xb2, xb2));
    const ull X0 = pk2(xa0, xb0), X1 = pk2(xa1, xb1), X2 = pk2(xa2, xb2);
    const ull SX = pk2(sxa, sxb);
    __syncthreads();

    float bestA[2] = {3.402823466e38f, 3.402823466e38f};
    float bestB[2] = {3.402823466e38f, 3.402823466e38f};
    int   iA[2] = {0, 0}, iB[2] = {0, 0};

    const int nb = w * 512;
#pragma unroll 2
    for (int n0 = 0; n0 < 512; n0 += 2) {
#pragma unroll
        for (int j = 0; j < 2; j++) {
            const int n = nb + n0 + j;
            const float4 q = p4[n];                          // broadcast LDS
            const ull QX = bc2(q.x), QY = bc2(q.y), QZ = bc2(q.z), QW = bc2(q.w);
            const ull DOT = add2(add2(mul2(X0, QX), mul2(X1, QY)), mul2(X2, QZ));
            const ull D2  = add2(sub2(SX, add2(DOT, DOT)), QW);
            float d2a, d2b;
            unpk2(d2a, d2b, D2);
            if (d2a < bestA[j]) { bestA[j] = d2a; iA[j] = n; }
            if (d2b < bestB[j]) { bestB[j] = d2b; iB[j] = n; }
        }
    }

    // Merge 2 chains per seed (exact tie-break: smaller n wins on equal d2).
    ull ka = mkkey(bestA[0], iA[0]);
    { const ull k1 = mkkey(bestA[1], iA[1]); if (k1 < ka) ka = k1; }
    ull kb = mkkey(bestB[0], iB[0]);
    { const ull k1 = mkkey(bestB[1], iB[1]); if (k1 < kb) kb = k1; }
    mg[w][lane]      = ka;
    mg[w][lane + 32] = kb;
    __syncthreads();

    if (tid < 64) {
        ull k = mg[0][tid];
#pragma unroll
        for (int r = 1; r < 8; r++) { const ull k2 = mg[r][tid]; if (k2 < k) k = k2; }
        g_idx[b * S_ + sbase + tid] = (int)(k & 0xFFFFFFFFu);
    }
}

// ---------------------------------------------------------------------------
// Kernel 2: gather (proven round-12 version). 4 rows/block, rolling cp.async,
// int4 idx + packed uint2 stores.
// ---------------------------------------------------------------------------
__global__ __launch_bounds__(256) void gather_kernel(const float* __restrict__ f) {
    extern __shared__ char gs[];
    float* rows = reinterpret_cast<float*>(gs);            // 4 * 4096 floats
    int*   sidx = reinterpret_cast<int*>(gs + 65536);      // 1024 ints
    const uint32_t sb = smem_u32(gs);
    const int b   = blockIdx.x / 192;
    const int c0  = (blockIdx.x % 192) * 4;
    const int tid = threadIdx.x;

    const char* src = reinterpret_cast<const char*>(f + ((size_t)(b * C_ + c0)) * N_);

    cp16(sb + 65536 + tid * 16, &g_idx[b * S_ + tid * 4]);
#pragma unroll
    for (int i = 0; i < 4; i++)
        cp16(sb + (tid + i * 256) * 16, src + (tid + i * 256) * 16);
    CP_COMMIT();
#pragma unroll
    for (int c = 1; c < 4; c++) {
#pragma unroll
        for (int i = 0; i < 4; i++)
            cp16(sb + (c * 1024 + tid + i * 256) * 16,
                 src + (size_t)(c * 1024 + tid + i * 256) * 16);
        CP_COMMIT();
    }

    CP_WAIT(3);
    __syncthreads();
    const int4 i4 = reinterpret_cast<const int4*>(sidx)[tid];

#define GPROC(c)                                                            \
    do {                                                                    \
        const float* row = rows + (c) * 4096;                               \
        const __half h0 = __float2half(row[i4.x]);                          \
        const __half h1 = __float2half(row[i4.y]);                          \
        const __half h2 = __float2half(row[i4.z]);                          \
        const __half h3 = __float2half(row[i4.w]);                          \
        uint2 pk;                                                           \
        pk.x = (uint32_t)__half_as_ushort(h0) |                             \
               ((uint32_t)__half_as_ushort(h1) << 16);                      \
        pk.y = (uint32_t)__half_as_ushort(h2) |                             \
               ((uint32_t)__half_as_ushort(h3) << 16);                      \
        *reinterpret_cast<uint2*>(                                          \
            &g_Af[(size_t)(c0 + (c)) * M_ + b * S_ + tid * 4]) = pk;        \
    } while (0)

    GPROC(0);
    CP_WAIT(2); __syncthreads();
    GPROC(1);
    CP_WAIT(1); __syncthreads();
    GPROC(2);
    CP_WAIT(0); __syncthreads();
    GPROC(3);
#undef GPROC
}

// ---------------------------------------------------------------------------
// Kernel 2b: round W to fp16 (single term).
// ---------------------------------------------------------------------------
__global__ __launch_bounds__(256) void wconv_kernel(const float* __restrict__ W) {
    const int i = blockIdx.x * 256 + threadIdx.x;
    if (i < O_ * C_) g_Bf[i] = __float2half(W[i]);
}

// ---------------------------------------------------------------------------
// Kernel 3: mma.sync fp16 GEMM (proven round-12 version).
// ---------------------------------------------------------------------------
#define ARR_AF 0
#define ARR_BF 4352
#define STAGE  7424
#define NSTG   8
#define GEMM_SMEM (NSTG * STAGE)

__global__ __launch_bounds__(256, 3) void gemm_kernel(const float* __restrict__ bias,
                                                      float* __restrict__ out) {
    extern __shared__ char smem[];
    const uint32_t sb = smem_u32(smem);
    const int tid  = threadIdx.x;
    const int lane = tid & 31;
    const int wid  = tid >> 5;
    const int warp_m = wid & 3;
    const int warp_n = wid >> 2;
    const int m0 = blockIdx.x * 128;
    const int n0 = blockIdx.y * 64;

    const int akrow = tid >> 4;
    const int aseg  = tid & 15;
    const __half* gA = g_Af + (size_t)akrow * M_ + m0 + aseg * 8;
    const uint32_t dA = (uint32_t)(akrow * 272 + aseg * 16);
    const int brow = (tid >> 1) & 63;
    const int bseg = tid & 1;
    const bool bact = tid < 128;
    const __half* gB = g_Bf + (size_t)(n0 + brow) * C_ + bseg * 8;
    const uint32_t dB = (uint32_t)(brow * 48 + bseg * 16);

#define ISSUE(kc, stg)                                                    \
    do {                                                                  \
        const uint32_t s0 = sb + (stg) * STAGE;                           \
        cp16(s0 + ARR_AF + dA, gA + (size_t)(kc) * (16 * M_));            \
        if (bact) cp16(s0 + ARR_BF + dB, gB + (kc) * 16);                 \
    } while (0)

    ISSUE(0, 0); CP_COMMIT();
    ISSUE(1, 1); CP_COMMIT();
    ISSUE(2, 2); CP_COMMIT();
    ISSUE(3, 3); CP_COMMIT();
    ISSUE(4, 4); CP_COMMIT();

    float acc[2][4][4];
#pragma unroll
    for (int i = 0; i < 2; i++)
#pragma unroll
        for (int j = 0; j < 4; j++)
#pragma unroll
            for (int p = 0; p < 4; p++) acc[i][j][p] = 0.f;

    const uint32_t aOff = (uint32_t)(((lane & 7) + ((lane >> 4) & 1) * 8) * 272
                                     + (warp_m * 32 + ((lane >> 3) & 1) * 8) * 2);
    const uint32_t bOff = (uint32_t)((warp_n * 32 + (lane & 7) + ((lane >> 4) << 3)) * 48
                                     + ((lane >> 3) & 1) * 16);

    uint32_t aF[2][2][4];
    uint32_t bF[2][2][4];

    CP_WAIT(4);
    __syncthreads();
    ldsm4t(aF[0][0], sb + ARR_AF + aOff);
    ldsm4t(aF[0][1], sb + ARR_AF + aOff + 32);
    ldsm4(bF[0][0], sb + ARR_BF + bOff);
    ldsm4(bF[0][1], sb + ARR_BF + bOff + 16 * 48);

#define STEP(c, n, kc)                                                     \
    do {                                                                   \
        if ((kc) + 1 < 48) {                                               \
            CP_WAIT(3);                                                    \
            __syncthreads();                                               \
            const uint32_t stn = sb + (((kc) + 1) & 7) * STAGE;            \
            ldsm4t(aF[n][0], stn + ARR_AF + aOff);                         \
            ldsm4t(aF[n][1], stn + ARR_AF + aOff + 32);                    \
            ldsm4(bF[n][0], stn + ARR_BF + bOff);                          \
            ldsm4(bF[n][1], stn + ARR_BF + bOff + 16 * 48);                \
            if ((kc) + 5 < 48) ISSUE((kc) + 5, ((kc) + 5) & 7);            \
            CP_COMMIT();                                                   \
        }                                                                  \
        _Pragma("unroll")                                                  \
        for (int mt = 0; mt < 2; mt++)                                     \
            _Pragma("unroll")                                              \
            for (int nt = 0; nt < 4; nt++)                                 \
                mma_f16(acc[mt][nt], aF[c][mt],                            \
                        &bF[c][nt >> 1][(nt & 1) * 2]);                    \
    } while (0)

#pragma unroll 1
    for (int kc = 0; kc < 48; kc += 2) {
        STEP(0, 1, kc);
        STEP(1, 0, kc + 1);
    }

    const int g  = lane >> 2;
    const int t4 = lane & 3;
    const int bbatch = m0 >> 10;
#pragma unroll
    for (int mt = 0; mt < 2; mt++) {
        const int m = m0 + warp_m * 32 + mt * 16 + g;
        const int slo = m & 1023;
#pragma unroll
        for (int nt = 0; nt < 4; nt++) {
            const int n = n0 + warp_n * 32 + nt * 8 + t4 * 2;
            const float b0v = __ldg(bias + n);
            const float b1v = __ldg(bias + n + 1);
            float* o0 = out + ((size_t)(bbatch * O_ + n)) * S_ + slo;
            float* o1 = out + ((size_t)(bbatch * O_ + n + 1)) * S_ + slo;
            o0[0] = acc[mt][nt][0] + b0v;
            o1[0] = acc[mt][nt][1] + b1v;
            o0[8] = acc[mt][nt][2] + b0v;
            o1[8] = acc[mt][nt][3] + b1v;
        }
    }
}

// ---------------------------------------------------------------------------
extern "C" void kernel_launch(void* const* d_in, const int* in_sizes, int n_in,
                              void* d_out, int out_size) {
    const float* seed = (const float*)d_in[0];   // [16,1024,3]
    const float* pl   = (const float*)d_in[1];   // [16,4096,3]
    const float* fl   = (const float*)d_in[2];   // [16,768,4096]
    const float* Wt   = (const float*)d_in[3];   // [256,768]
    const float* bias = (const float*)d_in[4];   // [256]
    float* out = (float*)d_out;                  // [16,256,1024]

    cudaFuncSetAttribute(argmin_kernel, cudaFuncAttributeMaxDynamicSharedMemorySize, 65536);
    cudaFuncSetAttribute(gather_kernel, cudaFuncAttributeMaxDynamicSharedMemorySize, 69632);
    cudaFuncSetAttribute(gemm_kernel, cudaFuncAttributeMaxDynamicSharedMemorySize, GEMM_SMEM);

    argmin_kernel<<<256, 256, 65536>>>(seed, pl);
    wconv_kernel<<<(O_ * C_ + 255) / 256, 256>>>(Wt);
    gather_kernel<<<B_ * 192, 256, 69632>>>(fl);
    gemm_kernel<<<dim3(M_ / 128, O_ / 64), 256, GEMM_SMEM>>>(bias, out);
}

// round 14
// speedup vs baseline: 1.4244x; 1.1016x over previous
#include <cuda_runtime.h>
#include <cuda_bf16.h>
#include <cuda_fp16.h>
#include <cstdint>

#define B_ 16
#define S_ 1024
#define N_ 4096
#define C_ 768
#define O_ 256
#define M_ (B_ * S_)   // 16384

// ---------------------------------------------------------------------------
// Scratch (__device__ globals; allocation-free rule). A is K-MAJOR, fp16.
// ---------------------------------------------------------------------------
__device__ int      g_idx[M_];
__device__ __half   g_Af[(size_t)C_ * M_];
__device__ __half   g_Bf[O_ * C_];

// ---------------------------------------------------------------------------
// Base-ISA (compute_103-safe) PTX helpers
// ---------------------------------------------------------------------------
__device__ __forceinline__ uint32_t smem_u32(const void* p) {
    uint32_t a;
    asm("{ .reg .u64 t; cvta.to.shared.u64 t, %1; cvt.u32.u64 %0, t; }" : "=r"(a) : "l"(p));
    return a;
}
__device__ __forceinline__ void cp16(uint32_t dst, const void* src) {
    asm volatile("cp.async.cg.shared.global [%0], [%1], 16;"
                 :: "r"(dst), "l"(src) : "memory");
}
#define CP_COMMIT() asm volatile("cp.async.commit_group;" ::: "memory")
#define CP_WAIT(n)  asm volatile("cp.async.wait_group %0;" :: "n"(n) : "memory")

__device__ __forceinline__ void ldsm4(uint32_t* r, uint32_t addr) {
    asm volatile("ldmatrix.sync.aligned.m8n8.x4.shared.b16 {%0,%1,%2,%3}, [%4];"
                 : "=r"(r[0]), "=r"(r[1]), "=r"(r[2]), "=r"(r[3]) : "r"(addr));
}
__device__ __forceinline__ void ldsm4t(uint32_t* r, uint32_t addr) {
    asm volatile("ldmatrix.sync.aligned.m8n8.x4.trans.shared.b16 {%0,%1,%2,%3}, [%4];"
                 : "=r"(r[0]), "=r"(r[1]), "=r"(r[2]), "=r"(r[3]) : "r"(addr));
}
__device__ __forceinline__ void mma_f16(float* c, const uint32_t* a, const uint32_t* b) {
    asm volatile("mma.sync.aligned.m16n8k16.row.col.f32.f16.f16.f32 "
                 "{%0,%1,%2,%3}, {%4,%5,%6,%7}, {%8,%9}, {%0,%1,%2,%3};"
                 : "+f"(c[0]), "+f"(c[1]), "+f"(c[2]), "+f"(c[3])
                 : "r"(a[0]), "r"(a[1]), "r"(a[2]), "r"(a[3]), "r"(b[0]), "r"(b[1]));
}

// ---- packed fp32x2 (per-lane IEEE rn, identical to __fmul_rn/__fadd_rn) ----
typedef unsigned long long ull;
__device__ __forceinline__ ull pk2(float a, float b) {
    ull r;
    asm("mov.b64 %0, {%1, %2};" : "=l"(r) : "r"(__float_as_uint(a)), "r"(__float_as_uint(b)));
    return r;
}
__device__ __forceinline__ ull bc2(float v) {
    ull r;
    asm("mov.b64 %0, {%1, %1};" : "=l"(r) : "r"(__float_as_uint(v)));
    return r;
}
__device__ __forceinline__ ull mul2(ull a, ull b) {
    ull d; asm("mul.rn.f32x2 %0, %1, %2;" : "=l"(d) : "l"(a), "l"(b)); return d;
}
__device__ __forceinline__ ull add2(ull a, ull b) {
    ull d; asm("add.rn.f32x2 %0, %1, %2;" : "=l"(d) : "l"(a), "l"(b)); return d;
}
__device__ __forceinline__ ull sub2(ull a, ull b) {
    return add2(a, b ^ 0x8000000080000000ull);
}
__device__ __forceinline__ void unpk2(float& lo, float& hi, ull v) {
    unsigned a, b;
    asm("mov.b64 {%0, %1}, %2;" : "=r"(a), "=r"(b) : "l"(v));
    lo = __uint_as_float(a); hi = __uint_as_float(b);
}
__device__ __forceinline__ ull mkkey(float d2, int n) {
    const unsigned u = __float_as_uint(d2);
    const unsigned ord = u ^ (((unsigned)((int)u >> 31)) | 0x80000000u);
    return ((ull)ord << 32) | (unsigned)n;
}

// ---------------------------------------------------------------------------
// Kernel 1: argmin, f32x2-packed (proven round-13 version).
// ---------------------------------------------------------------------------
__global__ __launch_bounds__(256) void argmin_kernel(const float* __restrict__ seed,
                                                     const float* __restrict__ pl) {
    extern __shared__ float4 p4[];                 // 4096 * 16B = 64KB
    __shared__ ull mg[8][64];
    const int bx   = blockIdx.x;
    const int b    = bx >> 4;
    const int tid  = threadIdx.x;
    const int w    = tid >> 5;
    const int lane = tid & 31;
    const int sbase = (bx & 15) << 6;

    for (int n = tid; n < N_; n += 256) {
        const float* pp = pl + ((size_t)b * N_ + n) * 3;
        const float p0 = pp[0], p1 = pp[1], p2 = pp[2];
        const float spp = __fadd_rn(__fadd_rn(__fmul_rn(p0, p0), __fmul_rn(p1, p1)),
                                    __fmul_rn(p2, p2));
        p4[n] = make_float4(p0, p1, p2, spp);
    }

    const float* sa = seed + ((size_t)b * S_ + sbase + lane) * 3;
    const float* sc = seed + ((size_t)b * S_ + sbase + 32 + lane) * 3;
    const float xa0 = sa[0], xa1 = sa[1], xa2 = sa[2];
    const float xb0 = sc[0], xb1 = sc[1], xb2 = sc[2];
    const float sxa = __fadd_rn(__fadd_rn(__fmul_rn(xa0, xa0), __fmul_rn(xa1, xa1)),
                                __fmul_rn(xa2, xa2));
    const float sxb = __fadd_rn(__fadd_rn(__fmul_rn(xb0, xb0), __fmul_rn(xb1, xb1)),
                                __fmul_rn(xb2, xb2));
    const ull X0 = pk2(xa0, xb0), X1 = pk2(xa1, xb1), X2 = pk2(xa2, xb2);
    const ull SX = pk2(sxa, sxb);
    __syncthreads();

    float bestA[2] = {3.402823466e38f, 3.402823466e38f};
    float bestB[2] = {3.402823466e38f, 3.402823466e38f};
    int   iA[2] = {0, 0}, iB[2] = {0, 0};

    const int nb = w * 512;
#pragma unroll 2
    for (int n0 = 0; n0 < 512; n0 += 2) {
#pragma unroll
        for (int j = 0; j < 2; j++) {
            const int n = nb + n0 + j;
            const float4 q = p4[n];
            const ull QX = bc2(q.x), QY = bc2(q.y), QZ = bc2(q.z), QW = bc2(q.w);
            const ull DOT = add2(add2(mul2(X0, QX), mul2(X1, QY)), mul2(X2, QZ));
            const ull D2  = add2(sub2(SX, add2(DOT, DOT)), QW);
            float d2a, d2b;
            unpk2(d2a, d2b, D2);
            if (d2a < bestA[j]) { bestA[j] = d2a; iA[j] = n; }
            if (d2b < bestB[j]) { bestB[j] = d2b; iB[j] = n; }
        }
    }

    ull ka = mkkey(bestA[0], iA[0]);
    { const ull k1 = mkkey(bestA[1], iA[1]); if (k1 < ka) ka = k1; }
    ull kb = mkkey(bestB[0], iB[0]);
    { const ull k1 = mkkey(bestB[1], iB[1]); if (k1 < kb) kb = k1; }
    mg[w][lane]      = ka;
    mg[w][lane + 32] = kb;
    __syncthreads();

    if (tid < 64) {
        ull k = mg[0][tid];
#pragma unroll
        for (int r = 1; r < 8; r++) { const ull k2 = mg[r][tid]; if (k2 < k) k = k2; }
        g_idx[b * S_ + sbase + tid] = (int)(k & 0xFFFFFFFFu);
    }
}

// ---------------------------------------------------------------------------
// Kernel 2: gather (proven round-12 version).
// ---------------------------------------------------------------------------
__global__ __launch_bounds__(256) void gather_kernel(const float* __restrict__ f) {
    extern __shared__ char gs[];
    float* rows = reinterpret_cast<float*>(gs);
    int*   sidx = reinterpret_cast<int*>(gs + 65536);
    const uint32_t sb = smem_u32(gs);
    const int b   = blockIdx.x / 192;
    const int c0  = (blockIdx.x % 192) * 4;
    const int tid = threadIdx.x;

    const char* src = reinterpret_cast<const char*>(f + ((size_t)(b * C_ + c0)) * N_);

    cp16(sb + 65536 + tid * 16, &g_idx[b * S_ + tid * 4]);
#pragma unroll
    for (int i = 0; i < 4; i++)
        cp16(sb + (tid + i * 256) * 16, src + (tid + i * 256) * 16);
    CP_COMMIT();
#pragma unroll
    for (int c = 1; c < 4; c++) {
#pragma unroll
        for (int i = 0; i < 4; i++)
            cp16(sb + (c * 1024 + tid + i * 256) * 16,
                 src + (size_t)(c * 1024 + tid + i * 256) * 16);
        CP_COMMIT();
    }

    CP_WAIT(3);
    __syncthreads();
    const int4 i4 = reinterpret_cast<const int4*>(sidx)[tid];

#define GPROC(c)                                                            \
    do {                                                                    \
        const float* row = rows + (c) * 4096;                               \
        const __half h0 = __float2half(row[i4.x]);                          \
        const __half h1 = __float2half(row[i4.y]);                          \
        const __half h2 = __float2half(row[i4.z]);                          \
        const __half h3 = __float2half(row[i4.w]);                          \
        uint2 pk;                                                           \
        pk.x = (uint32_t)__half_as_ushort(h0) |                             \
               ((uint32_t)__half_as_ushort(h1) << 16);                      \
        pk.y = (uint32_t)__half_as_ushort(h2) |                             \
               ((uint32_t)__half_as_ushort(h3) << 16);                      \
        *reinterpret_cast<uint2*>(                                          \
            &g_Af[(size_t)(c0 + (c)) * M_ + b * S_ + tid * 4]) = pk;        \
    } while (0)

    GPROC(0);
    CP_WAIT(2); __syncthreads();
    GPROC(1);
    CP_WAIT(1); __syncthreads();
    GPROC(2);
    CP_WAIT(0); __syncthreads();
    GPROC(3);
#undef GPROC
}

// ---------------------------------------------------------------------------
// Kernel 2b: round W to fp16.
// ---------------------------------------------------------------------------
__global__ __launch_bounds__(256) void wconv_kernel(const float* __restrict__ W) {
    const int i = blockIdx.x * 256 + threadIdx.x;
    if (i < O_ * C_) g_Bf[i] = __float2half(W[i]);
}

// ---------------------------------------------------------------------------
// Kernel 3: mma.sync fp16 GEMM, single term: D = Af*Bf.
// CTA 256m x 64n, 256 thr, warps 4m x 2n, warp tile m64 x n32, k16 chunks.
// Grid 64x4 = 256 CTAs, 2 CTAs/SM -> single wave on 296 slots.
// 16 MMAs per warp per barrier (2x amortization vs 128m tile).
// B fragments: double-buffered prefetch (proven). A fragments: in-loop
// ldsm.trans per mt, interleaved with MMAs (reg budget: ~115 <= 128).
// A k-major: 16 krows x 512B data, 528B stride (round-6-verified conflict-
// free addressing). Stage: Af 8448 | Bf 3072 = 11520B; 8 stages = 92160B.
// ---------------------------------------------------------------------------
#define ARR_AF 0
#define ARR_BF 8448
#define STAGE  11520
#define NSTG   8
#define GEMM_SMEM (NSTG * STAGE)

__global__ __launch_bounds__(256, 2) void gemm_kernel(const float* __restrict__ bias,
                                                      float* __restrict__ out) {
    extern __shared__ char smem[];
    const uint32_t sb = smem_u32(smem);
    const int tid  = threadIdx.x;
    const int lane = tid & 31;
    const int wid  = tid >> 5;
    const int warp_m = wid & 3;      // 4 m-warps (m64 each)
    const int warp_n = wid >> 2;     // 2 n-warps (n32 each)
    const int m0 = blockIdx.x * 256;
    const int n0 = blockIdx.y * 64;

    // cp.async assignment.
    // A (k-major): krow = tid>>4 (0..15), segs tid&15 and +16 (m +128).
    const int akrow = tid >> 4;
    const int aseg  = tid & 15;
    const __half* gA = g_Af + (size_t)akrow * M_ + m0 + aseg * 8;
    const uint32_t dA = (uint32_t)(akrow * 528 + aseg * 16);
    // B (row-major, 64 rows x 2 segs of 16B): threads 0..127.
    const int brow = (tid >> 1) & 63;
    const int bseg = tid & 1;
    const bool bact = tid < 128;
    const __half* gB = g_Bf + (size_t)(n0 + brow) * C_ + bseg * 8;
    const uint32_t dB = (uint32_t)(brow * 48 + bseg * 16);

#define ISSUE(kc, stg)                                                    \
    do {                                                                  \
        const uint32_t s0 = sb + (stg) * STAGE;                           \
        const size_t ga = (size_t)(kc) * (16 * M_);                       \
        cp16(s0 + ARR_AF + dA,       gA + ga);                            \
        cp16(s0 + ARR_AF + dA + 256, gA + ga + 128);                      \
        if (bact) cp16(s0 + ARR_BF + dB, gB + (kc) * 16);                 \
    } while (0)

    ISSUE(0, 0); CP_COMMIT();
    ISSUE(1, 1); CP_COMMIT();
    ISSUE(2, 2); CP_COMMIT();
    ISSUE(3, 3); CP_COMMIT();
    ISSUE(4, 4); CP_COMMIT();

    float acc[4][4][4];
#pragma unroll
    for (int i = 0; i < 4; i++)
#pragma unroll
        for (int j = 0; j < 4; j++)
#pragma unroll
            for (int p = 0; p < 4; p++) acc[i][j][p] = 0.f;

    // ldmatrix.trans A addressing (round-6-verified): k-rows x 528B,
    // m-cols x 2B; per-mt step +32B (16 m-cols).
    const uint32_t aOff = (uint32_t)(((lane & 7) + ((lane >> 4) & 1) * 8) * 528
                                     + (warp_m * 64 + ((lane >> 3) & 1) * 8) * 2);
    // ldmatrix B addressing (verified): 48B rows.
    const uint32_t bOff = (uint32_t)((warp_n * 32 + (lane & 7) + ((lane >> 4) << 3)) * 48
                                     + ((lane >> 3) & 1) * 16);

    uint32_t bF[2][2][4];            // [buf][ntp][reg]

    // Prologue: stage 0 B fragments -> buf 0.
    CP_WAIT(4);
    __syncthreads();
    ldsm4(bF[0][0], sb + ARR_BF + bOff);
    ldsm4(bF[0][1], sb + ARR_BF + bOff + 16 * 48);

#define STEP(c, n, kc)                                                     \
    do {                                                                   \
        if ((kc) + 1 < 48) {                                               \
            CP_WAIT(3);                                                    \
            __syncthreads();                                               \
            const uint32_t stn = sb + (((kc) + 1) & 7) * STAGE;            \
            ldsm4(bF[n][0], stn + ARR_BF + bOff);                          \
            ldsm4(bF[n][1], stn + ARR_BF + bOff + 16 * 48);                \
            if ((kc) + 5 < 48) ISSUE((kc) + 5, ((kc) + 5) & 7);            \
            CP_COMMIT();                                                   \
        }                                                                  \
        const uint32_t stc = sb + ((kc) & 7) * STAGE;                      \
        _Pragma("unroll")                                                  \
        for (int mt = 0; mt < 4; mt++) {                                   \
            uint32_t ah[4];                                                \
            ldsm4t(ah, stc + ARR_AF + aOff + mt * 32);                     \
            _Pragma("unroll")                                              \
            for (int nt = 0; nt < 4; nt++)                                 \
                mma_f16(acc[mt][nt], ah,                                   \
                        &bF[c][nt >> 1][(nt & 1) * 2]);                    \
        }                                                                  \
    } while (0)

#pragma unroll 1
    for (int kc = 0; kc < 48; kc += 2) {
        STEP(0, 1, kc);
        STEP(1, 0, kc + 1);
    }

    // Epilogue
    const int g  = lane >> 2;
    const int t4 = lane & 3;
    const int bbatch = m0 >> 10;       // 256-row tiles never straddle a batch
#pragma unroll
    for (int mt = 0; mt < 4; mt++) {
        const int m = m0 + warp_m * 64 + mt * 16 + g;
        const int slo = m & 1023;
#pragma unroll
        for (int nt = 0; nt < 4; nt++) {
            const int n = n0 + warp_n * 32 + nt * 8 + t4 * 2;
            const float b0v = __ldg(bias + n);
            const float b1v = __ldg(bias + n + 1);
            float* o0 = out + ((size_t)(bbatch * O_ + n)) * S_ + slo;
            float* o1 = out + ((size_t)(bbatch * O_ + n + 1)) * S_ + slo;
            o0[0] = acc[mt][nt][0] + b0v;
            o1[0] = acc[mt][nt][1] + b1v;
            o0[8] = acc[mt][nt][2] + b0v;
            o1[8] = acc[mt][nt][3] + b1v;
        }
    }
}

// ---------------------------------------------------------------------------
extern "C" void kernel_launch(void* const* d_in, const int* in_sizes, int n_in,
                              void* d_out, int out_size) {
    const float* seed = (const float*)d_in[0];   // [16,1024,3]
    const float* pl   = (const float*)d_in[1];   // [16,4096,3]
    const float* fl   = (const float*)d_in[2];   // [16,768,4096]
    const float* Wt   = (const float*)d_in[3];   // [256,768]
    const float* bias = (const float*)d_in[4];   // [256]
    float* out = (float*)d_out;                  // [16,256,1024]

    cudaFuncSetAttribute(argmin_kernel, cudaFuncAttributeMaxDynamicSharedMemorySize, 65536);
    cudaFuncSetAttribute(gather_kernel, cudaFuncAttributeMaxDynamicSharedMemorySize, 69632);
    cudaFuncSetAttribute(gemm_kernel, cudaFuncAttributeMaxDynamicSharedMemorySize, GEMM_SMEM);

    argmin_kernel<<<256, 256, 65536>>>(seed, pl);
    wconv_kernel<<<(O_ * C_ + 255) / 256, 256>>>(Wt);
    gather_kernel<<<B_ * 192, 256, 69632>>>(fl);
    gemm_kernel<<<dim3(M_ / 256, O_ / 64), 256, GEMM_SMEM>>>(bias, out);
}

// round 15
// speedup vs baseline: 1.4249x; 1.0003x over previous
#include <cuda_runtime.h>
#include <cuda_bf16.h>
#include <cuda_fp16.h>
#include <cstdint>

#define B_ 16
#define S_ 1024
#define N_ 4096
#define C_ 768
#define O_ 256
#define M_ (B_ * S_)   // 16384

// ---------------------------------------------------------------------------
// Scratch (__device__ globals; allocation-free rule). A is K-MAJOR, fp16.
// ---------------------------------------------------------------------------
__device__ int      g_idx[M_];
__device__ __half   g_Af[(size_t)C_ * M_];
__device__ __half   g_Bf[O_ * C_];

// ---------------------------------------------------------------------------
// Base-ISA (compute_103-safe) PTX helpers
// ---------------------------------------------------------------------------
__device__ __forceinline__ uint32_t smem_u32(const void* p) {
    uint32_t a;
    asm("{ .reg .u64 t; cvta.to.shared.u64 t, %1; cvt.u32.u64 %0, t; }" : "=r"(a) : "l"(p));
    return a;
}
__device__ __forceinline__ void cp16(uint32_t dst, const void* src) {
    asm volatile("cp.async.cg.shared.global [%0], [%1], 16;"
                 :: "r"(dst), "l"(src) : "memory");
}
#define CP_COMMIT() asm volatile("cp.async.commit_group;" ::: "memory")
#define CP_WAIT(n)  asm volatile("cp.async.wait_group %0;" :: "n"(n) : "memory")

__device__ __forceinline__ void ldsm4(uint32_t* r, uint32_t addr) {
    asm volatile("ldmatrix.sync.aligned.m8n8.x4.shared.b16 {%0,%1,%2,%3}, [%4];"
                 : "=r"(r[0]), "=r"(r[1]), "=r"(r[2]), "=r"(r[3]) : "r"(addr));
}
__device__ __forceinline__ void ldsm4t(uint32_t* r, uint32_t addr) {
    asm volatile("ldmatrix.sync.aligned.m8n8.x4.trans.shared.b16 {%0,%1,%2,%3}, [%4];"
                 : "=r"(r[0]), "=r"(r[1]), "=r"(r[2]), "=r"(r[3]) : "r"(addr));
}
__device__ __forceinline__ void mma_f16(float* c, const uint32_t* a, const uint32_t* b) {
    asm volatile("mma.sync.aligned.m16n8k16.row.col.f32.f16.f16.f32 "
                 "{%0,%1,%2,%3}, {%4,%5,%6,%7}, {%8,%9}, {%0,%1,%2,%3};"
                 : "+f"(c[0]), "+f"(c[1]), "+f"(c[2]), "+f"(c[3])
                 : "r"(a[0]), "r"(a[1]), "r"(a[2]), "r"(a[3]), "r"(b[0]), "r"(b[1]));
}

// ---- packed fp32x2 (per-lane IEEE rn, identical to __fmul_rn/__fadd_rn) ----
typedef unsigned long long ull;
__device__ __forceinline__ ull pk2(float a, float b) {
    ull r;
    asm("mov.b64 %0, {%1, %2};" : "=l"(r) : "r"(__float_as_uint(a)), "r"(__float_as_uint(b)));
    return r;
}
__device__ __forceinline__ ull bc2(float v) {
    ull r;
    asm("mov.b64 %0, {%1, %1};" : "=l"(r) : "r"(__float_as_uint(v)));
    return r;
}
__device__ __forceinline__ ull mul2(ull a, ull b) {
    ull d; asm("mul.rn.f32x2 %0, %1, %2;" : "=l"(d) : "l"(a), "l"(b)); return d;
}
__device__ __forceinline__ ull add2(ull a, ull b) {
    ull d; asm("add.rn.f32x2 %0, %1, %2;" : "=l"(d) : "l"(a), "l"(b)); return d;
}
__device__ __forceinline__ ull sub2(ull a, ull b) {
    return add2(a, b ^ 0x8000000080000000ull);
}
__device__ __forceinline__ void unpk2(float& lo, float& hi, ull v) {
    unsigned a, b;
    asm("mov.b64 {%0, %1}, %2;" : "=r"(a), "=r"(b) : "l"(v));
    lo = __uint_as_float(a); hi = __uint_as_float(b);
}
__device__ __forceinline__ ull mkkey(float d2, int n) {
    const unsigned u = __float_as_uint(d2);
    const unsigned ord = u ^ (((unsigned)((int)u >> 31)) | 0x80000000u);
    return ((ull)ord << 32) | (unsigned)n;
}

// ---------------------------------------------------------------------------
// Kernel 1: argmin, f32x2-packed (proven round-13 version).
// ---------------------------------------------------------------------------
__global__ __launch_bounds__(256) void argmin_kernel(const float* __restrict__ seed,
                                                     const float* __restrict__ pl) {
    extern __shared__ float4 p4[];                 // 4096 * 16B = 64KB
    __shared__ ull mg[8][64];
    const int bx   = blockIdx.x;
    const int b    = bx >> 4;
    const int tid  = threadIdx.x;
    const int w    = tid >> 5;
    const int lane = tid & 31;
    const int sbase = (bx & 15) << 6;

    for (int n = tid; n < N_; n += 256) {
        const float* pp = pl + ((size_t)b * N_ + n) * 3;
        const float p0 = pp[0], p1 = pp[1], p2 = pp[2];
        const float spp = __fadd_rn(__fadd_rn(__fmul_rn(p0, p0), __fmul_rn(p1, p1)),
                                    __fmul_rn(p2, p2));
        p4[n] = make_float4(p0, p1, p2, spp);
    }

    const float* sa = seed + ((size_t)b * S_ + sbase + lane) * 3;
    const float* sc = seed + ((size_t)b * S_ + sbase + 32 + lane) * 3;
    const float xa0 = sa[0], xa1 = sa[1], xa2 = sa[2];
    const float xb0 = sc[0], xb1 = sc[1], xb2 = sc[2];
    const float sxa = __fadd_rn(__fadd_rn(__fmul_rn(xa0, xa0), __fmul_rn(xa1, xa1)),
                                __fmul_rn(xa2, xa2));
    const float sxb = __fadd_rn(__fadd_rn(__fmul_rn(xb0, xb0), __fmul_rn(xb1, xb1)),
                                __fmul_rn(xb2, xb2));
    const ull X0 = pk2(xa0, xb0), X1 = pk2(xa1, xb1), X2 = pk2(xa2, xb2);
    const ull SX = pk2(sxa, sxb);
    __syncthreads();

    float bestA[2] = {3.402823466e38f, 3.402823466e38f};
    float bestB[2] = {3.402823466e38f, 3.402823466e38f};
    int   iA[2] = {0, 0}, iB[2] = {0, 0};

    const int nb = w * 512;
#pragma unroll 2
    for (int n0 = 0; n0 < 512; n0 += 2) {
#pragma unroll
        for (int j = 0; j < 2; j++) {
            const int n = nb + n0 + j;
            const float4 q = p4[n];
            const ull QX = bc2(q.x), QY = bc2(q.y), QZ = bc2(q.z), QW = bc2(q.w);
            const ull DOT = add2(add2(mul2(X0, QX), mul2(X1, QY)), mul2(X2, QZ));
            const ull D2  = add2(sub2(SX, add2(DOT, DOT)), QW);
            float d2a, d2b;
            unpk2(d2a, d2b, D2);
            if (d2a < bestA[j]) { bestA[j] = d2a; iA[j] = n; }
            if (d2b < bestB[j]) { bestB[j] = d2b; iB[j] = n; }
        }
    }

    ull ka = mkkey(bestA[0], iA[0]);
    { const ull k1 = mkkey(bestA[1], iA[1]); if (k1 < ka) ka = k1; }
    ull kb = mkkey(bestB[0], iB[0]);
    { const ull k1 = mkkey(bestB[1], iB[1]); if (k1 < kb) kb = k1; }
    mg[w][lane]      = ka;
    mg[w][lane + 32] = kb;
    __syncthreads();

    if (tid < 64) {
        ull k = mg[0][tid];
#pragma unroll
        for (int r = 1; r < 8; r++) { const ull k2 = mg[r][tid]; if (k2 < k) k = k2; }
        g_idx[b * S_ + sbase + tid] = (int)(k & 0xFFFFFFFFu);
    }
}

// ---------------------------------------------------------------------------
// Kernel 2: gather, 1 channel/block, 128 threads, single cp.async group.
// blockIdx.x = b*768 + c, so f row offset = blockIdx.x * 4096 floats.
// smem: row 16KB @0, idx 4KB @16384 -> 20.5KB -> 11 blocks/SM (44 warps):
// deep inter-block overlap hides the one load latency. Each thread: 8 seeds,
// 8 LDS lookups, pack -> one uint4 (16B) store. Conversion per element
// identical to prior rounds -> bit-identical output.
// ---------------------------------------------------------------------------
__global__ __launch_bounds__(128) void gather_kernel(const float* __restrict__ f) {
    extern __shared__ char gs[];
    float* row  = reinterpret_cast<float*>(gs);            // 4096 floats
    int*   sidx = reinterpret_cast<int*>(gs + 16384);      // 1024 ints
    const uint32_t sb = smem_u32(gs);
    const int bx  = blockIdx.x;
    const int b   = bx / 768;
    const int c   = bx - b * 768;
    const int tid = threadIdx.x;

    const char* src = reinterpret_cast<const char*>(f) + (size_t)bx * 16384;

    // One group: row (1024 segs) + idx (256 segs).
#pragma unroll
    for (int i = 0; i < 8; i++)
        cp16(sb + (tid + i * 128) * 16, src + (size_t)(tid + i * 128) * 16);
#pragma unroll
    for (int i = 0; i < 2; i++)
        cp16(sb + 16384 + (tid + i * 128) * 16, &g_idx[b * S_ + (tid + i * 128) * 4]);
    CP_COMMIT();
    CP_WAIT(0);
    __syncthreads();

    const int4 ia = reinterpret_cast<const int4*>(sidx)[tid * 2];
    const int4 ib = reinterpret_cast<const int4*>(sidx)[tid * 2 + 1];

    const __half h0 = __float2half(row[ia.x]);
    const __half h1 = __float2half(row[ia.y]);
    const __half h2 = __float2half(row[ia.z]);
    const __half h3 = __float2half(row[ia.w]);
    const __half h4 = __float2half(row[ib.x]);
    const __half h5 = __float2half(row[ib.y]);
    const __half h6 = __float2half(row[ib.z]);
    const __half h7 = __float2half(row[ib.w]);

    uint4 pk;
    pk.x = (uint32_t)__half_as_ushort(h0) | ((uint32_t)__half_as_ushort(h1) << 16);
    pk.y = (uint32_t)__half_as_ushort(h2) | ((uint32_t)__half_as_ushort(h3) << 16);
    pk.z = (uint32_t)__half_as_ushort(h4) | ((uint32_t)__half_as_ushort(h5) << 16);
    pk.w = (uint32_t)__half_as_ushort(h6) | ((uint32_t)__half_as_ushort(h7) << 16);
    *reinterpret_cast<uint4*>(&g_Af[(size_t)c * M_ + b * S_ + tid * 8]) = pk;
}

// ---------------------------------------------------------------------------
// Kernel 2b: round W to fp16.
// ---------------------------------------------------------------------------
__global__ __launch_bounds__(256) void wconv_kernel(const float* __restrict__ W) {
    const int i = blockIdx.x * 256 + threadIdx.x;
    if (i < O_ * C_) g_Bf[i] = __float2half(W[i]);
}

// ---------------------------------------------------------------------------
// Kernel 3: mma.sync fp16 GEMM (proven round-14 version).
// CTA 256m x 64n, warp tile m64 x n32, k16 chunks, 8-stage ring, 2 CTAs/SM.
// ---------------------------------------------------------------------------
#define ARR_AF 0
#define ARR_BF 8448
#define STAGE  11520
#define NSTG   8
#define GEMM_SMEM (NSTG * STAGE)

__global__ __launch_bounds__(256, 2) void gemm_kernel(const float* __restrict__ bias,
                                                      float* __restrict__ out) {
    extern __shared__ char smem[];
    const uint32_t sb = smem_u32(smem);
    const int tid  = threadIdx.x;
    const int lane = tid & 31;
    const int wid  = tid >> 5;
    const int warp_m = wid & 3;
    const int warp_n = wid >> 2;
    const int m0 = blockIdx.x * 256;
    const int n0 = blockIdx.y * 64;

    const int akrow = tid >> 4;
    const int aseg  = tid & 15;
    const __half* gA = g_Af + (size_t)akrow * M_ + m0 + aseg * 8;
    const uint32_t dA = (uint32_t)(akrow * 528 + aseg * 16);
    const int brow = (tid >> 1) & 63;
    const int bseg = tid & 1;
    const bool bact = tid < 128;
    const __half* gB = g_Bf + (size_t)(n0 + brow) * C_ + bseg * 8;
    const uint32_t dB = (uint32_t)(brow * 48 + bseg * 16);

#define ISSUE(kc, stg)                                                    \
    do {                                                                  \
        const uint32_t s0 = sb + (stg) * STAGE;                           \
        const size_t ga = (size_t)(kc) * (16 * M_);                       \
        cp16(s0 + ARR_AF + dA,       gA + ga);                            \
        cp16(s0 + ARR_AF + dA + 256, gA + ga + 128);                      \
        if (bact) cp16(s0 + ARR_BF + dB, gB + (kc) * 16);                 \
    } while (0)

    ISSUE(0, 0); CP_COMMIT();
    ISSUE(1, 1); CP_COMMIT();
    ISSUE(2, 2); CP_COMMIT();
    ISSUE(3, 3); CP_COMMIT();
    ISSUE(4, 4); CP_COMMIT();

    float acc[4][4][4];
#pragma unroll
    for (int i = 0; i < 4; i++)
#pragma unroll
        for (int j = 0; j < 4; j++)
#pragma unroll
            for (int p = 0; p < 4; p++) acc[i][j][p] = 0.f;

    const uint32_t aOff = (uint32_t)(((lane & 7) + ((lane >> 4) & 1) * 8) * 528
                                     + (warp_m * 64 + ((lane >> 3) & 1) * 8) * 2);
    const uint32_t bOff = (uint32_t)((warp_n * 32 + (lane & 7) + ((lane >> 4) << 3)) * 48
                                     + ((lane >> 3) & 1) * 16);

    uint32_t bF[2][2][4];

    CP_WAIT(4);
    __syncthreads();
    ldsm4(bF[0][0], sb + ARR_BF + bOff);
    ldsm4(bF[0][1], sb + ARR_BF + bOff + 16 * 48);

#define STEP(c, n, kc)                                                     \
    do {                                                                   \
        if ((kc) + 1 < 48) {                                               \
            CP_WAIT(3);                                                    \
            __syncthreads();                                               \
            const uint32_t stn = sb + (((kc) + 1) & 7) * STAGE;            \
            ldsm4(bF[n][0], stn + ARR_BF + bOff);                          \
            ldsm4(bF[n][1], stn + ARR_BF + bOff + 16 * 48);                \
            if ((kc) + 5 < 48) ISSUE((kc) + 5, ((kc) + 5) & 7);            \
            CP_COMMIT();                                                   \
        }                                                                  \
        const uint32_t stc = sb + ((kc) & 7) * STAGE;                      \
        _Pragma("unroll")                                                  \
        for (int mt = 0; mt < 4; mt++) {                                   \
            uint32_t ah[4];                                                \
            ldsm4t(ah, stc + ARR_AF + aOff + mt * 32);                     \
            _Pragma("unroll")                                              \
            for (int nt = 0; nt < 4; nt++)                                 \
                mma_f16(acc[mt][nt], ah,                                   \
                        &bF[c][nt >> 1][(nt & 1) * 2]);                    \
        }                                                                  \
    } while (0)

#pragma unroll 1
    for (int kc = 0; kc < 48; kc += 2) {
        STEP(0, 1, kc);
        STEP(1, 0, kc + 1);
    }

    const int g  = lane >> 2;
    const int t4 = lane & 3;
    const int bbatch = m0 >> 10;
#pragma unroll
    for (int mt = 0; mt < 4; mt++) {
        const int m = m0 + warp_m * 64 + mt * 16 + g;
        const int slo = m & 1023;
#pragma unroll
        for (int nt = 0; nt < 4; nt++) {
            const int n = n0 + warp_n * 32 + nt * 8 + t4 * 2;
            const float b0v = __ldg(bias + n);
            const float b1v = __ldg(bias + n + 1);
            float* o0 = out + ((size_t)(bbatch * O_ + n)) * S_ + slo;
            float* o1 = out + ((size_t)(bbatch * O_ + n + 1)) * S_ + slo;
            o0[0] = acc[mt][nt][0] + b0v;
            o1[0] = acc[mt][nt][1] + b1v;
            o0[8] = acc[mt][nt][2] + b0v;
            o1[8] = acc[mt][nt][3] + b1v;
        }
    }
}

// ---------------------------------------------------------------------------
extern "C" void kernel_launch(void* const* d_in, const int* in_sizes, int n_in,
                              void* d_out, int out_size) {
    const float* seed = (const float*)d_in[0];   // [16,1024,3]
    const float* pl   = (const float*)d_in[1];   // [16,4096,3]
    const float* fl   = (const float*)d_in[2];   // [16,768,4096]
    const float* Wt   = (const float*)d_in[3];   // [256,768]
    const float* bias = (const float*)d_in[4];   // [256]
    float* out = (float*)d_out;                  // [16,256,1024]

    cudaFuncSetAttribute(argmin_kernel, cudaFuncAttributeMaxDynamicSharedMemorySize, 65536);
    cudaFuncSetAttribute(gather_kernel, cudaFuncAttributeMaxDynamicSharedMemorySize, 20480);
    cudaFuncSetAttribute(gemm_kernel, cudaFuncAttributeMaxDynamicSharedMemorySize, GEMM_SMEM);

    argmin_kernel<<<256, 256, 65536>>>(seed, pl);
    wconv_kernel<<<(O_ * C_ + 255) / 256, 256>>>(Wt);
    gather_kernel<<<B_ * C_, 128, 20480>>>(fl);
    gemm_kernel<<<dim3(M_ / 256, O_ / 64), 256, GEMM_SMEM>>>(bias, out);
}